// round 11
// baseline (speedup 1.0000x reference)
#include <cuda_runtime.h>
#include <cuda_bf16.h>
#include <math.h>
#include <stdint.h>

// ---------------------------------------------------------------------------
// Problem constants
// ---------------------------------------------------------------------------
#define B_SZ    2
#define LSEQ    2048
#define DMODEL  1024
#define DINNER  2048
#define DSTATE  16
#define DTRANK  64
#define DCONV   4
#define M_ROWS  (B_SZ * LSEQ)            // 4096
#define XZ_COLS (2 * DINNER)             // 4096
#define XDBL_COLS (DTRANK + 2 * DSTATE)  // 96

#define NCHUNK  32
#define CLEN    (LSEQ / NCHUNK)          // 64
#define NSLICE  8
#define KSLICE  (DINNER / NSLICE)        // 256
#define XPN     128                      // padded N for x_proj tc-gemm

// ---------------------------------------------------------------------------
// Scratch
// ---------------------------------------------------------------------------
__device__ float g_xz  [(size_t)M_ROWS * XZ_COLS];
__device__ float g_xc  [(size_t)M_ROWS * DINNER];
__device__ float g_xdbl[(size_t)M_ROWS * XDBL_COLS];
__device__ float g_dt  [(size_t)M_ROWS * DINNER];
__device__ float g_y   [(size_t)M_ROWS * DINNER];
__device__ float g_xp2 [(size_t)NSLICE * M_ROWS * XPN];   // x_proj partials (padded)

__device__ float g_P [(size_t)B_SZ * DINNER * DSTATE * NCHUNK];
__device__ float g_S [(size_t)B_SZ * DINNER * DSTATE * NCHUNK];
__device__ float g_h0[(size_t)B_SZ * DINNER * DSTATE * NCHUNK];

__device__ __nv_bfloat16 g_xhi [(size_t)M_ROWS * DMODEL];
__device__ __nv_bfloat16 g_xlo [(size_t)M_ROWS * DMODEL];
__device__ __nv_bfloat16 g_wihi[(size_t)XZ_COLS * DMODEL];
__device__ __nv_bfloat16 g_wilo[(size_t)XZ_COLS * DMODEL];
__device__ __nv_bfloat16 g_yhi [(size_t)M_ROWS * DINNER];
__device__ __nv_bfloat16 g_ylo [(size_t)M_ROWS * DINNER];
__device__ __nv_bfloat16 g_wohi[(size_t)DMODEL * DINNER];
__device__ __nv_bfloat16 g_wolo[(size_t)DMODEL * DINNER];
__device__ __nv_bfloat16 g_xchi[(size_t)M_ROWS * DINNER];
__device__ __nv_bfloat16 g_xclo[(size_t)M_ROWS * DINNER];
__device__ __nv_bfloat16 g_xwhi[(size_t)XPN * DINNER];    // rows 96..127 stay zero
__device__ __nv_bfloat16 g_xwlo[(size_t)XPN * DINNER];
__device__ __nv_bfloat16 g_dthi[(size_t)M_ROWS * DTRANK];
__device__ __nv_bfloat16 g_dtlo[(size_t)M_ROWS * DTRANK];
__device__ __nv_bfloat16 g_dwhi[(size_t)DINNER * DTRANK];
__device__ __nv_bfloat16 g_dwlo[(size_t)DINNER * DTRANK];

// ---------------------------------------------------------------------------
// PTX helpers
// ---------------------------------------------------------------------------
__device__ __forceinline__ uint32_t smem_u32(const void* p) {
    uint32_t a;
    asm("{ .reg .u64 t; cvta.to.shared.u64 t, %1; cvt.u32.u64 %0, t; }" : "=r"(a) : "l"(p));
    return a;
}
__device__ __forceinline__ void cp_async16(uint32_t saddr, const void* gaddr) {
    asm volatile("cp.async.cg.shared.global [%0], [%1], 16;" :: "r"(saddr), "l"(gaddr));
}
#define CP_COMMIT()  asm volatile("cp.async.commit_group;" ::: "memory")
#define CP_WAIT1()   asm volatile("cp.async.wait_group 1;" ::: "memory")

__device__ __forceinline__ void ldsm_x4(uint32_t (&r)[4], uint32_t addr) {
    asm volatile("ldmatrix.sync.aligned.m8n8.x4.shared.b16 {%0,%1,%2,%3}, [%4];"
        : "=r"(r[0]), "=r"(r[1]), "=r"(r[2]), "=r"(r[3]) : "r"(addr));
}
__device__ __forceinline__ void mma_bf16(float (&d)[4],
                                         const uint32_t (&a)[4],
                                         uint32_t b0, uint32_t b1) {
    asm volatile(
        "mma.sync.aligned.m16n8k16.row.col.f32.bf16.bf16.f32 "
        "{%0,%1,%2,%3}, {%4,%5,%6,%7}, {%8,%9}, {%0,%1,%2,%3};"
        : "+f"(d[0]), "+f"(d[1]), "+f"(d[2]), "+f"(d[3])
        : "r"(a[0]), "r"(a[1]), "r"(a[2]), "r"(a[3]), "r"(b0), "r"(b1));
}

__device__ __forceinline__ void split_bf16x4(float4 v, uint2& ho, uint2& lo2) {
    __nv_bfloat162 h01 = __nv_bfloat162(__float2bfloat16(v.x), __float2bfloat16(v.y));
    __nv_bfloat162 h23 = __nv_bfloat162(__float2bfloat16(v.z), __float2bfloat16(v.w));
    __nv_bfloat162 l01 = __nv_bfloat162(__float2bfloat16(v.x - __bfloat162float(h01.x)),
                                        __float2bfloat16(v.y - __bfloat162float(h01.y)));
    __nv_bfloat162 l23 = __nv_bfloat162(__float2bfloat16(v.z - __bfloat162float(h23.x)),
                                        __float2bfloat16(v.w - __bfloat162float(h23.y)));
    ho.x  = *reinterpret_cast<uint32_t*>(&h01);  ho.y  = *reinterpret_cast<uint32_t*>(&h23);
    lo2.x = *reinterpret_cast<uint32_t*>(&l01);  lo2.y = *reinterpret_cast<uint32_t*>(&l23);
}

// ---------------------------------------------------------------------------
// Split-bf16 TC GEMM: C[M,N](+slice) = A[M,K-range]*B[N,K-range]^T
// ---------------------------------------------------------------------------
#define TCBM 128
#define TCBN 128
#define TCBK 32
#define PITCHB 80
#define OPTILE (TCBM * PITCHB)
#define STAGEB (4 * OPTILE)
#define TCSMEM (2 * STAGEB)

__device__ __forceinline__ void fill_op128(uint32_t sbase, const __nv_bfloat16* g,
                                           int grow0, int lda, int k0, int tid) {
#pragma unroll
    for (int t = 0; t < 4; t++) {
        int u = tid + t * 128;
        int r = u >> 2, seg = u & 3;
        const __nv_bfloat16* gp = g + (size_t)(grow0 + r) * lda + k0 + seg * 8;
        cp_async16(sbase + r * PITCHB + seg * 16, gp);
    }
}
__device__ __forceinline__ void fill_stage(uint32_t s, const __nv_bfloat16* Ahi,
                                           const __nv_bfloat16* Alo,
                                           const __nv_bfloat16* Bhi,
                                           const __nv_bfloat16* Blo,
                                           int mrow, int ncol, int lda, int k0, int tid) {
    fill_op128(s + 0 * OPTILE, Ahi, mrow, lda, k0, tid);
    fill_op128(s + 1 * OPTILE, Alo, mrow, lda, k0, tid);
    fill_op128(s + 2 * OPTILE, Bhi, ncol, lda, k0, tid);
    fill_op128(s + 3 * OPTILE, Blo, ncol, lda, k0, tid);
}

template<int EPI>
__global__ void __launch_bounds__(128, 2)
tc_gemm_kernel(int lda, int klen,
               const __nv_bfloat16* __restrict__ Ahi, const __nv_bfloat16* __restrict__ Alo,
               const __nv_bfloat16* __restrict__ Bhi, const __nv_bfloat16* __restrict__ Blo,
               float* __restrict__ C, int ldc, size_t c_slice_stride,
               const float* __restrict__ bias)
{
    extern __shared__ char smem[];
    const uint32_t sb = smem_u32(smem);

    const int tid  = threadIdx.x;
    const int lane = tid & 31;
    const int w    = tid >> 5;
    const int wm   = w & 1;
    const int wn   = w >> 1;
    const int mrow = blockIdx.y * TCBM;
    const int ncol = blockIdx.x * TCBN;
    const int kbeg = blockIdx.z * klen;
    C += (size_t)blockIdx.z * c_slice_stride;

    float acc[4][8][4];
#pragma unroll
    for (int i = 0; i < 4; i++)
#pragma unroll
        for (int j = 0; j < 8; j++)
#pragma unroll
            for (int e = 0; e < 4; e++) acc[i][j][e] = 0.f;

    const int nc = klen / TCBK;

    fill_stage(sb, Ahi, Alo, Bhi, Blo, mrow, ncol, lda, kbeg, tid);
    CP_COMMIT();

    const int a_row = (lane & 15);
    const int a_cb  = (lane >> 4);
    const int b_row = (lane & 7) + ((lane >> 4) << 3);
    const int b_cb  = (lane >> 3) & 1;

    for (int c = 0; c < nc; c++) {
        if (c + 1 < nc) {
            fill_stage(sb + ((c + 1) & 1) * STAGEB, Ahi, Alo, Bhi, Blo,
                       mrow, ncol, lda, kbeg + (c + 1) * TCBK, tid);
        }
        CP_COMMIT();
        CP_WAIT1();
        __syncthreads();

        const uint32_t s = sb + (c & 1) * STAGEB;
        const uint32_t sAhi = s + 0 * OPTILE;
        const uint32_t sAlo = s + 1 * OPTILE;
        const uint32_t sBhi = s + 2 * OPTILE;
        const uint32_t sBlo = s + 3 * OPTILE;

#pragma unroll
        for (int ks = 0; ks < 2; ks++) {
            uint32_t ahi[4][4], alo[4][4];
            uint32_t bhi[4][4], blo[4][4];
#pragma unroll
            for (int mi = 0; mi < 4; mi++) {
                uint32_t ao = (uint32_t)((wm * 64 + mi * 16 + a_row) * PITCHB + ks * 32 + a_cb * 16);
                ldsm_x4(ahi[mi], sAhi + ao);
                ldsm_x4(alo[mi], sAlo + ao);
            }
#pragma unroll
            for (int j = 0; j < 4; j++) {
                uint32_t bo = (uint32_t)((wn * 64 + j * 16 + b_row) * PITCHB + ks * 32 + b_cb * 16);
                ldsm_x4(bhi[j], sBhi + bo);
                ldsm_x4(blo[j], sBlo + bo);
            }
#pragma unroll
            for (int mi = 0; mi < 4; mi++)
#pragma unroll
                for (int nj = 0; nj < 8; nj++) {
                    const int j = nj >> 1, h = (nj & 1) * 2;
                    mma_bf16(acc[mi][nj], ahi[mi], bhi[j][h], bhi[j][h + 1]);
                }
#pragma unroll
            for (int mi = 0; mi < 4; mi++)
#pragma unroll
                for (int nj = 0; nj < 8; nj++) {
                    const int j = nj >> 1, h = (nj & 1) * 2;
                    mma_bf16(acc[mi][nj], ahi[mi], blo[j][h], blo[j][h + 1]);
                }
#pragma unroll
            for (int mi = 0; mi < 4; mi++)
#pragma unroll
                for (int nj = 0; nj < 8; nj++) {
                    const int j = nj >> 1, h = (nj & 1) * 2;
                    mma_bf16(acc[mi][nj], alo[mi], bhi[j][h], bhi[j][h + 1]);
                }
        }
        __syncthreads();
    }

    const int er = lane >> 2;
    const int ec = (lane & 3) * 2;
#pragma unroll
    for (int mi = 0; mi < 4; mi++) {
#pragma unroll
        for (int nj = 0; nj < 8; nj++) {
            int r0 = mrow + wm * 64 + mi * 16 + er;
            int cc = ncol + wn * 64 + nj * 8 + ec;
            float2 v0 = make_float2(acc[mi][nj][0], acc[mi][nj][1]);
            float2 v1 = make_float2(acc[mi][nj][2], acc[mi][nj][3]);
            if (EPI == 1) {
                float b0 = bias[cc], b1 = bias[cc + 1];
                v0.x += b0; v0.y += b1; v1.x += b0; v1.y += b1;
                v0.x = (v0.x > 20.f) ? v0.x : log1pf(__expf(v0.x));
                v0.y = (v0.y > 20.f) ? v0.y : log1pf(__expf(v0.y));
                v1.x = (v1.x > 20.f) ? v1.x : log1pf(__expf(v1.x));
                v1.y = (v1.y > 20.f) ? v1.y : log1pf(__expf(v1.y));
            }
            *reinterpret_cast<float2*>(C + (size_t)r0 * ldc + cc) = v0;
            *reinterpret_cast<float2*>(C + (size_t)(r0 + 8) * ldc + cc) = v1;
        }
    }
}

// ---------------------------------------------------------------------------
// Merged fp32 -> (bf16 hi, lo) conversions
// ---------------------------------------------------------------------------
#define CVT_N1 (M_ROWS * DMODEL / 4)
#define CVT_N2 (XZ_COLS * DMODEL / 4)
#define CVT_N3 (DMODEL * DINNER / 4)
#define CVT_N4 (XDBL_COLS * DINNER / 4)
#define CVT_N5 (DINNER * DTRANK / 4)

__global__ void cvt_all_kernel(const float* __restrict__ x,
                               const float* __restrict__ wi,
                               const float* __restrict__ wo,
                               const float* __restrict__ xw,
                               const float* __restrict__ dw)
{
    int i = blockIdx.x * blockDim.x + threadIdx.x;
    const float* src; __nv_bfloat16 *hi, *lo; int off;
    if (i < CVT_N1)                         { src = x;  hi = g_xhi;  lo = g_xlo;  off = i; }
    else if (i < CVT_N1+CVT_N2)             { src = wi; hi = g_wihi; lo = g_wilo; off = i - CVT_N1; }
    else if (i < CVT_N1+CVT_N2+CVT_N3)      { src = wo; hi = g_wohi; lo = g_wolo; off = i - CVT_N1 - CVT_N2; }
    else if (i < CVT_N1+CVT_N2+CVT_N3+CVT_N4) { src = xw; hi = g_xwhi; lo = g_xwlo; off = i - CVT_N1 - CVT_N2 - CVT_N3; }
    else if (i < CVT_N1+CVT_N2+CVT_N3+CVT_N4+CVT_N5) { src = dw; hi = g_dwhi; lo = g_dwlo; off = i - CVT_N1 - CVT_N2 - CVT_N3 - CVT_N4; }
    else return;

    float4 v = reinterpret_cast<const float4*>(src)[off];
    uint2 ho, lo2;
    split_bf16x4(v, ho, lo2);
    reinterpret_cast<uint2*>(hi)[off] = ho;
    reinterpret_cast<uint2*>(lo)[off] = lo2;
}

// ---------------------------------------------------------------------------
// Depthwise causal conv1d + bias + SiLU; also emits bf16 hi/lo of xc.
// ---------------------------------------------------------------------------
__global__ void conv_silu_kernel(const float* __restrict__ conv_w,
                                 const float* __restrict__ conv_b)
{
    int idx = blockIdx.x * blockDim.x + threadIdx.x;
    if (idx >= M_ROWS * DINNER / 4) return;
    int d4 = (idx % (DINNER / 4)) * 4;
    int m  = idx / (DINNER / 4);
    int t  = m % LSEQ;
    int b  = m / LSEQ;

    float4 acc = *reinterpret_cast<const float4*>(conv_b + d4);
#pragma unroll
    for (int j = 0; j < DCONV; j++) {
        int tt = t - (DCONV - 1) + j;
        if (tt >= 0) {
            float4 v = *reinterpret_cast<const float4*>(
                g_xz + (size_t)(b * LSEQ + tt) * XZ_COLS + d4);
            acc.x += v.x * __ldg(conv_w + (d4 + 0) * DCONV + j);
            acc.y += v.y * __ldg(conv_w + (d4 + 1) * DCONV + j);
            acc.z += v.z * __ldg(conv_w + (d4 + 2) * DCONV + j);
            acc.w += v.w * __ldg(conv_w + (d4 + 3) * DCONV + j);
        }
    }
    float4 o;
    o.x = acc.x / (1.f + __expf(-acc.x));
    o.y = acc.y / (1.f + __expf(-acc.y));
    o.z = acc.z / (1.f + __expf(-acc.z));
    o.w = acc.w / (1.f + __expf(-acc.w));
    size_t off = (size_t)m * DINNER + d4;
    *reinterpret_cast<float4*>(g_xc + off) = o;
    uint2 ho, lo2;
    split_bf16x4(o, ho, lo2);
    reinterpret_cast<uint2*>(g_xchi)[off / 4] = ho;
    reinterpret_cast<uint2*>(g_xclo)[off / 4] = lo2;
}

// ---------------------------------------------------------------------------
// x_proj reduce: sum partials -> g_xdbl; also emit dt-rank hi/lo for dt_proj.
// ---------------------------------------------------------------------------
__global__ void xproj_reduce_kernel()
{
    int i = blockIdx.x * blockDim.x + threadIdx.x;
    if (i >= M_ROWS * XDBL_COLS) return;
    int r = i / XDBL_COLS, c = i % XDBL_COLS;
    float s = 0.f;
#pragma unroll
    for (int z = 0; z < NSLICE; z++)
        s += g_xp2[(size_t)z * M_ROWS * XPN + (size_t)r * XPN + c];
    g_xdbl[i] = s;
    if (c < DTRANK) {
        __nv_bfloat16 h = __float2bfloat16(s);
        g_dthi[(size_t)r * DTRANK + c] = h;
        g_dtlo[(size_t)r * DTRANK + c] = __float2bfloat16(s - __bfloat162float(h));
    }
}

// ---------------------------------------------------------------------------
// Chunked selective scan (pass1 / combine / pass2), NCHUNK=32
// ---------------------------------------------------------------------------
__global__ void scan_pass1(const float* __restrict__ A_log)
{
    const int lane16 = threadIdx.x & 15;
    const int grp    = threadIdx.x >> 4;
    const int b      = blockIdx.x / (DINNER / 16);
    const int d      = (blockIdx.x % (DINNER / 16)) * 16 + grp;
    const int ck     = blockIdx.y;
    const int t0     = ck * CLEN;

    const float Ad = -__expf(A_log[d * DSTATE + lane16]);

    const float* dt_p = g_dt   + ((size_t)b * LSEQ + t0) * DINNER + d;
    const float* x_p  = g_xc   + ((size_t)b * LSEQ + t0) * DINNER + d;
    const float* bc_p = g_xdbl + ((size_t)b * LSEQ + t0) * XDBL_COLS;

    float h = 0.f, p = 1.f;
    float d0 = dt_p[0], x0 = x_p[0];
    float B0 = bc_p[DTRANK + lane16];
    float d1 = dt_p[DINNER], x1 = x_p[DINNER];
    float B1 = bc_p[XDBL_COLS + DTRANK + lane16];

    for (int t = 0; t < CLEN; t++) {
        float d2 = 0.f, x2 = 0.f, B2 = 0.f;
        if (t + 2 < CLEN) {
            d2 = dt_p[(size_t)(t + 2) * DINNER];
            x2 = x_p [(size_t)(t + 2) * DINNER];
            B2 = bc_p[(size_t)(t + 2) * XDBL_COLS + DTRANK + lane16];
        }
        float dA = __expf(d0 * Ad);
        h = dA * h + (d0 * x0) * B0;
        p *= dA;
        d0 = d1; x0 = x1; B0 = B1;
        d1 = d2; x1 = x2; B1 = B2;
    }
    size_t idx = (((size_t)b * DINNER + d) * DSTATE + lane16) * NCHUNK + ck;
    g_P[idx] = p;
    g_S[idx] = h;
}

__global__ void scan_combine()
{
    int i = blockIdx.x * blockDim.x + threadIdx.x;
    if (i >= B_SZ * DINNER * DSTATE) return;
    size_t base = (size_t)i * NCHUNK;
    float h = 0.f;
#pragma unroll
    for (int c = 0; c < NCHUNK; c++) {
        g_h0[base + c] = h;
        h = g_S[base + c] + g_P[base + c] * h;
    }
}

__global__ void scan_pass2(const float* __restrict__ A_log,
                           const float* __restrict__ D_param)
{
    const int lane16 = threadIdx.x & 15;
    const int grp    = threadIdx.x >> 4;
    const int b      = blockIdx.x / (DINNER / 16);
    const int d      = (blockIdx.x % (DINNER / 16)) * 16 + grp;
    const int ck     = blockIdx.y;
    const int t0     = ck * CLEN;

    const float Ad = -__expf(A_log[d * DSTATE + lane16]);
    const float Dd = D_param[d];

    const float* dt_p = g_dt   + ((size_t)b * LSEQ + t0) * DINNER + d;
    const float* x_p  = g_xc   + ((size_t)b * LSEQ + t0) * DINNER + d;
    const float* bc_p = g_xdbl + ((size_t)b * LSEQ + t0) * XDBL_COLS;
    float*       y_p  = g_y    + ((size_t)b * LSEQ + t0) * DINNER + d;

    float h = g_h0[(((size_t)b * DINNER + d) * DSTATE + lane16) * NCHUNK + ck];

    float d0 = dt_p[0], x0 = x_p[0];
    float B0 = bc_p[DTRANK + lane16];
    float C0 = bc_p[DTRANK + DSTATE + lane16];
    float d1 = dt_p[DINNER], x1 = x_p[DINNER];
    float B1 = bc_p[XDBL_COLS + DTRANK + lane16];
    float C1 = bc_p[XDBL_COLS + DTRANK + DSTATE + lane16];

    for (int t = 0; t < CLEN; t++) {
        float d2 = 0.f, x2 = 0.f, B2 = 0.f, C2 = 0.f;
        if (t + 2 < CLEN) {
            d2 = dt_p[(size_t)(t + 2) * DINNER];
            x2 = x_p [(size_t)(t + 2) * DINNER];
            B2 = bc_p[(size_t)(t + 2) * XDBL_COLS + DTRANK + lane16];
            C2 = bc_p[(size_t)(t + 2) * XDBL_COLS + DTRANK + DSTATE + lane16];
        }
        float dA = __expf(d0 * Ad);
        h = dA * h + (d0 * x0) * B0;
        float p = h * C0;
        p += __shfl_xor_sync(0xffffffffu, p, 1);
        p += __shfl_xor_sync(0xffffffffu, p, 2);
        p += __shfl_xor_sync(0xffffffffu, p, 4);
        p += __shfl_xor_sync(0xffffffffu, p, 8);
        if (lane16 == 0)
            y_p[(size_t)t * DINNER] = p + Dd * x0;
        d0 = d1; x0 = x1; B0 = B1; C0 = C1;
        d1 = d2; x1 = x2; B1 = B2; C1 = C2;
    }
}

// ---------------------------------------------------------------------------
// Gate + split-bf16 convert (coalesced, standalone)
// ---------------------------------------------------------------------------
__global__ void gate_cvt_kernel()
{
    int idx = blockIdx.x * blockDim.x + threadIdx.x;
    if (idx >= M_ROWS * DINNER / 4) return;
    int d4 = (idx % (DINNER / 4)) * 4;
    int m  = idx / (DINNER / 4);
    float4 z = *reinterpret_cast<const float4*>(g_xz + (size_t)m * XZ_COLS + DINNER + d4);
    float4 y = *reinterpret_cast<const float4*>(g_y + (size_t)m * DINNER + d4);
    float4 v;
    v.x = y.x * (z.x / (1.f + __expf(-z.x)));
    v.y = y.y * (z.y / (1.f + __expf(-z.y)));
    v.z = y.z * (z.z / (1.f + __expf(-z.z)));
    v.w = y.w * (z.w / (1.f + __expf(-z.w)));
    uint2 ho, lo2;
    split_bf16x4(v, ho, lo2);
    size_t off = ((size_t)m * DINNER + d4) / 4;
    reinterpret_cast<uint2*>(g_yhi)[off] = ho;
    reinterpret_cast<uint2*>(g_ylo)[off] = lo2;
}

// ---------------------------------------------------------------------------
// Launch
// ---------------------------------------------------------------------------
extern "C" void kernel_launch(void* const* d_in, const int* in_sizes, int n_in,
                              void* d_out, int out_size)
{
    const float* x         = (const float*)d_in[0];
    const float* in_proj_w = (const float*)d_in[1];
    const float* conv_w    = (const float*)d_in[2];
    const float* conv_b    = (const float*)d_in[3];
    const float* x_proj_w  = (const float*)d_in[4];
    const float* dt_proj_w = (const float*)d_in[5];
    const float* dt_proj_b = (const float*)d_in[6];
    const float* A_log     = (const float*)d_in[7];
    const float* D_param   = (const float*)d_in[8];
    const float* out_proj_w= (const float*)d_in[9];
    float* out = (float*)d_out;

    float *xz, *dt, *xp2;
    cudaGetSymbolAddress((void**)&xz,  g_xz);
    cudaGetSymbolAddress((void**)&dt,  g_dt);
    cudaGetSymbolAddress((void**)&xp2, g_xp2);
    __nv_bfloat16 *xhi, *xlo, *wihi, *wilo, *yhi, *ylo, *wohi, *wolo;
    __nv_bfloat16 *xchi, *xclo, *xwhi, *xwlo, *dthi, *dtlo, *dwhi, *dwlo;
    cudaGetSymbolAddress((void**)&xhi,  g_xhi);
    cudaGetSymbolAddress((void**)&xlo,  g_xlo);
    cudaGetSymbolAddress((void**)&wihi, g_wihi);
    cudaGetSymbolAddress((void**)&wilo, g_wilo);
    cudaGetSymbolAddress((void**)&yhi,  g_yhi);
    cudaGetSymbolAddress((void**)&ylo,  g_ylo);
    cudaGetSymbolAddress((void**)&wohi, g_wohi);
    cudaGetSymbolAddress((void**)&wolo, g_wolo);
    cudaGetSymbolAddress((void**)&xchi, g_xchi);
    cudaGetSymbolAddress((void**)&xclo, g_xclo);
    cudaGetSymbolAddress((void**)&xwhi, g_xwhi);
    cudaGetSymbolAddress((void**)&xwlo, g_xwlo);
    cudaGetSymbolAddress((void**)&dthi, g_dthi);
    cudaGetSymbolAddress((void**)&dtlo, g_dtlo);
    cudaGetSymbolAddress((void**)&dwhi, g_dwhi);
    cudaGetSymbolAddress((void**)&dwlo, g_dwlo);

    cudaFuncSetAttribute(tc_gemm_kernel<0>, cudaFuncAttributeMaxDynamicSharedMemorySize, TCSMEM);
    cudaFuncSetAttribute(tc_gemm_kernel<1>, cudaFuncAttributeMaxDynamicSharedMemorySize, TCSMEM);

    // 0) merged split-bf16 conversions
    {
        int n = CVT_N1 + CVT_N2 + CVT_N3 + CVT_N4 + CVT_N5;
        cvt_all_kernel<<<(n + 255) / 256, 256>>>(x, in_proj_w, out_proj_w, x_proj_w, dt_proj_w);
    }

    // 1) in_proj: xz = x * Wi^T
    {
        dim3 grid(XZ_COLS / TCBN, M_ROWS / TCBM, 1);
        tc_gemm_kernel<0><<<grid, 128, TCSMEM>>>(DMODEL, DMODEL,
            xhi, xlo, wihi, wilo, xz, XZ_COLS, 0, nullptr);
    }

    // 2) conv + silu (+ hi/lo emit)
    {
        int n = M_ROWS * DINNER / 4;
        conv_silu_kernel<<<(n + 255) / 256, 256>>>(conv_w, conv_b);
    }

    // 3) x_proj on tensor cores, split-K x8; then reduce (+ dt hi/lo emit)
    {
        dim3 grid(1, M_ROWS / TCBM, NSLICE);
        tc_gemm_kernel<0><<<grid, 128, TCSMEM>>>(DINNER, KSLICE,
            xchi, xclo, xwhi, xwlo, xp2, XPN, (size_t)M_ROWS * XPN, nullptr);
        int n = M_ROWS * XDBL_COLS;
        xproj_reduce_kernel<<<(n + 255) / 256, 256>>>();
    }

    // 4) dt_proj on tensor cores (K=64) + bias + softplus epilogue
    {
        dim3 grid(DINNER / TCBN, M_ROWS / TCBM, 1);
        tc_gemm_kernel<1><<<grid, 128, TCSMEM>>>(DTRANK, DTRANK,
            dthi, dtlo, dwhi, dwlo, dt, DINNER, 0, dt_proj_b);
    }

    // 5) chunked parallel scan (NCHUNK=32)
    {
        dim3 grid(B_SZ * DINNER / 16, NCHUNK);
        scan_pass1<<<grid, 256>>>(A_log);
        int n = B_SZ * DINNER * DSTATE;
        scan_combine<<<(n + 255) / 256, 256>>>();
        scan_pass2<<<grid, 256>>>(A_log, D_param);
    }

    // 6) gate + split convert
    {
        int n = M_ROWS * DINNER / 4;
        gate_cvt_kernel<<<(n + 255) / 256, 256>>>();
    }

    // 7) out_proj
    {
        dim3 grid(DMODEL / TCBN, M_ROWS / TCBM, 1);
        tc_gemm_kernel<0><<<grid, 128, TCSMEM>>>(DINNER, DINNER,
            yhi, ylo, wohi, wolo, out, DMODEL, 0, nullptr);
    }
}

// round 12
// speedup vs baseline: 1.0298x; 1.0298x over previous
#include <cuda_runtime.h>
#include <cuda_bf16.h>
#include <math.h>
#include <stdint.h>

// ---------------------------------------------------------------------------
// Problem constants
// ---------------------------------------------------------------------------
#define B_SZ    2
#define LSEQ    2048
#define DMODEL  1024
#define DINNER  2048
#define DSTATE  16
#define DTRANK  64
#define DCONV   4
#define M_ROWS  (B_SZ * LSEQ)            // 4096
#define XZ_COLS (2 * DINNER)             // 4096
#define XDBL_COLS (DTRANK + 2 * DSTATE)  // 96

#define NCHUNK  16
#define CLEN    (LSEQ / NCHUNK)          // 128
#define NSLICE  4
#define KSLICE  (DINNER / NSLICE)        // 512
#define XPN     128                      // padded N for x_proj tc-gemm

// ---------------------------------------------------------------------------
// Scratch
// ---------------------------------------------------------------------------
__device__ float g_xz  [(size_t)M_ROWS * XZ_COLS];
__device__ float g_xc  [(size_t)M_ROWS * DINNER];
__device__ float g_xdbl[(size_t)M_ROWS * XDBL_COLS];
__device__ float g_dt  [(size_t)M_ROWS * DINNER];
__device__ float g_y   [(size_t)M_ROWS * DINNER];
__device__ float g_xp2 [(size_t)NSLICE * M_ROWS * XPN];   // x_proj partials (padded)

__device__ float g_P [(size_t)B_SZ * DINNER * DSTATE * NCHUNK];
__device__ float g_S [(size_t)B_SZ * DINNER * DSTATE * NCHUNK];
__device__ float g_h0[(size_t)B_SZ * DINNER * DSTATE * NCHUNK];

__device__ __nv_bfloat16 g_xhi [(size_t)M_ROWS * DMODEL];
__device__ __nv_bfloat16 g_xlo [(size_t)M_ROWS * DMODEL];
__device__ __nv_bfloat16 g_wihi[(size_t)XZ_COLS * DMODEL];
__device__ __nv_bfloat16 g_wilo[(size_t)XZ_COLS * DMODEL];
__device__ __nv_bfloat16 g_yhi [(size_t)M_ROWS * DINNER];
__device__ __nv_bfloat16 g_ylo [(size_t)M_ROWS * DINNER];
__device__ __nv_bfloat16 g_wohi[(size_t)DMODEL * DINNER];
__device__ __nv_bfloat16 g_wolo[(size_t)DMODEL * DINNER];
__device__ __nv_bfloat16 g_xchi[(size_t)M_ROWS * DINNER];
__device__ __nv_bfloat16 g_xclo[(size_t)M_ROWS * DINNER];
__device__ __nv_bfloat16 g_xwhi[(size_t)XPN * DINNER];    // rows 96..127 stay zero
__device__ __nv_bfloat16 g_xwlo[(size_t)XPN * DINNER];
__device__ __nv_bfloat16 g_dthi[(size_t)M_ROWS * DTRANK];
__device__ __nv_bfloat16 g_dtlo[(size_t)M_ROWS * DTRANK];
__device__ __nv_bfloat16 g_dwhi[(size_t)DINNER * DTRANK];
__device__ __nv_bfloat16 g_dwlo[(size_t)DINNER * DTRANK];

// ---------------------------------------------------------------------------
// PTX helpers
// ---------------------------------------------------------------------------
__device__ __forceinline__ uint32_t smem_u32(const void* p) {
    uint32_t a;
    asm("{ .reg .u64 t; cvta.to.shared.u64 t, %1; cvt.u32.u64 %0, t; }" : "=r"(a) : "l"(p));
    return a;
}
__device__ __forceinline__ void cp_async16(uint32_t saddr, const void* gaddr) {
    asm volatile("cp.async.cg.shared.global [%0], [%1], 16;" :: "r"(saddr), "l"(gaddr));
}
#define CP_COMMIT()  asm volatile("cp.async.commit_group;" ::: "memory")
#define CP_WAIT1()   asm volatile("cp.async.wait_group 1;" ::: "memory")

__device__ __forceinline__ void ldsm_x4(uint32_t (&r)[4], uint32_t addr) {
    asm volatile("ldmatrix.sync.aligned.m8n8.x4.shared.b16 {%0,%1,%2,%3}, [%4];"
        : "=r"(r[0]), "=r"(r[1]), "=r"(r[2]), "=r"(r[3]) : "r"(addr));
}
__device__ __forceinline__ void mma_bf16(float (&d)[4],
                                         const uint32_t (&a)[4],
                                         uint32_t b0, uint32_t b1) {
    asm volatile(
        "mma.sync.aligned.m16n8k16.row.col.f32.bf16.bf16.f32 "
        "{%0,%1,%2,%3}, {%4,%5,%6,%7}, {%8,%9}, {%0,%1,%2,%3};"
        : "+f"(d[0]), "+f"(d[1]), "+f"(d[2]), "+f"(d[3])
        : "r"(a[0]), "r"(a[1]), "r"(a[2]), "r"(a[3]), "r"(b0), "r"(b1));
}

__device__ __forceinline__ void split_bf16x4(float4 v, uint2& ho, uint2& lo2) {
    __nv_bfloat162 h01 = __nv_bfloat162(__float2bfloat16(v.x), __float2bfloat16(v.y));
    __nv_bfloat162 h23 = __nv_bfloat162(__float2bfloat16(v.z), __float2bfloat16(v.w));
    __nv_bfloat162 l01 = __nv_bfloat162(__float2bfloat16(v.x - __bfloat162float(h01.x)),
                                        __float2bfloat16(v.y - __bfloat162float(h01.y)));
    __nv_bfloat162 l23 = __nv_bfloat162(__float2bfloat16(v.z - __bfloat162float(h23.x)),
                                        __float2bfloat16(v.w - __bfloat162float(h23.y)));
    ho.x  = *reinterpret_cast<uint32_t*>(&h01);  ho.y  = *reinterpret_cast<uint32_t*>(&h23);
    lo2.x = *reinterpret_cast<uint32_t*>(&l01);  lo2.y = *reinterpret_cast<uint32_t*>(&l23);
}

// ---------------------------------------------------------------------------
// Split-bf16 TC GEMM: C[M,N](+slice) = A[M,K-range]*B[N,K-range]^T
// ---------------------------------------------------------------------------
#define TCBM 128
#define TCBN 128
#define TCBK 32
#define PITCHB 80
#define OPTILE (TCBM * PITCHB)
#define STAGEB (4 * OPTILE)
#define TCSMEM (2 * STAGEB)

__device__ __forceinline__ void fill_op128(uint32_t sbase, const __nv_bfloat16* g,
                                           int grow0, int lda, int k0, int tid) {
#pragma unroll
    for (int t = 0; t < 4; t++) {
        int u = tid + t * 128;
        int r = u >> 2, seg = u & 3;
        const __nv_bfloat16* gp = g + (size_t)(grow0 + r) * lda + k0 + seg * 8;
        cp_async16(sbase + r * PITCHB + seg * 16, gp);
    }
}
__device__ __forceinline__ void fill_stage(uint32_t s, const __nv_bfloat16* Ahi,
                                           const __nv_bfloat16* Alo,
                                           const __nv_bfloat16* Bhi,
                                           const __nv_bfloat16* Blo,
                                           int mrow, int ncol, int lda, int k0, int tid) {
    fill_op128(s + 0 * OPTILE, Ahi, mrow, lda, k0, tid);
    fill_op128(s + 1 * OPTILE, Alo, mrow, lda, k0, tid);
    fill_op128(s + 2 * OPTILE, Bhi, ncol, lda, k0, tid);
    fill_op128(s + 3 * OPTILE, Blo, ncol, lda, k0, tid);
}

template<int EPI>
__global__ void __launch_bounds__(128, 2)
tc_gemm_kernel(int lda, int klen,
               const __nv_bfloat16* __restrict__ Ahi, const __nv_bfloat16* __restrict__ Alo,
               const __nv_bfloat16* __restrict__ Bhi, const __nv_bfloat16* __restrict__ Blo,
               float* __restrict__ C, int ldc, size_t c_slice_stride,
               const float* __restrict__ bias)
{
    extern __shared__ char smem[];
    const uint32_t sb = smem_u32(smem);

    const int tid  = threadIdx.x;
    const int lane = tid & 31;
    const int w    = tid >> 5;
    const int wm   = w & 1;
    const int wn   = w >> 1;
    const int mrow = blockIdx.y * TCBM;
    const int ncol = blockIdx.x * TCBN;
    const int kbeg = blockIdx.z * klen;
    C += (size_t)blockIdx.z * c_slice_stride;

    float acc[4][8][4];
#pragma unroll
    for (int i = 0; i < 4; i++)
#pragma unroll
        for (int j = 0; j < 8; j++)
#pragma unroll
            for (int e = 0; e < 4; e++) acc[i][j][e] = 0.f;

    const int nc = klen / TCBK;

    fill_stage(sb, Ahi, Alo, Bhi, Blo, mrow, ncol, lda, kbeg, tid);
    CP_COMMIT();

    const int a_row = (lane & 15);
    const int a_cb  = (lane >> 4);
    const int b_row = (lane & 7) + ((lane >> 4) << 3);
    const int b_cb  = (lane >> 3) & 1;

    for (int c = 0; c < nc; c++) {
        if (c + 1 < nc) {
            fill_stage(sb + ((c + 1) & 1) * STAGEB, Ahi, Alo, Bhi, Blo,
                       mrow, ncol, lda, kbeg + (c + 1) * TCBK, tid);
        }
        CP_COMMIT();
        CP_WAIT1();
        __syncthreads();

        const uint32_t s = sb + (c & 1) * STAGEB;
        const uint32_t sAhi = s + 0 * OPTILE;
        const uint32_t sAlo = s + 1 * OPTILE;
        const uint32_t sBhi = s + 2 * OPTILE;
        const uint32_t sBlo = s + 3 * OPTILE;

#pragma unroll
        for (int ks = 0; ks < 2; ks++) {
            uint32_t ahi[4][4], alo[4][4];
            uint32_t bhi[4][4], blo[4][4];
#pragma unroll
            for (int mi = 0; mi < 4; mi++) {
                uint32_t ao = (uint32_t)((wm * 64 + mi * 16 + a_row) * PITCHB + ks * 32 + a_cb * 16);
                ldsm_x4(ahi[mi], sAhi + ao);
                ldsm_x4(alo[mi], sAlo + ao);
            }
#pragma unroll
            for (int j = 0; j < 4; j++) {
                uint32_t bo = (uint32_t)((wn * 64 + j * 16 + b_row) * PITCHB + ks * 32 + b_cb * 16);
                ldsm_x4(bhi[j], sBhi + bo);
                ldsm_x4(blo[j], sBlo + bo);
            }
#pragma unroll
            for (int mi = 0; mi < 4; mi++)
#pragma unroll
                for (int nj = 0; nj < 8; nj++) {
                    const int j = nj >> 1, h = (nj & 1) * 2;
                    mma_bf16(acc[mi][nj], ahi[mi], bhi[j][h], bhi[j][h + 1]);
                }
#pragma unroll
            for (int mi = 0; mi < 4; mi++)
#pragma unroll
                for (int nj = 0; nj < 8; nj++) {
                    const int j = nj >> 1, h = (nj & 1) * 2;
                    mma_bf16(acc[mi][nj], ahi[mi], blo[j][h], blo[j][h + 1]);
                }
#pragma unroll
            for (int mi = 0; mi < 4; mi++)
#pragma unroll
                for (int nj = 0; nj < 8; nj++) {
                    const int j = nj >> 1, h = (nj & 1) * 2;
                    mma_bf16(acc[mi][nj], alo[mi], bhi[j][h], bhi[j][h + 1]);
                }
        }
        __syncthreads();
    }

    const int er = lane >> 2;
    const int ec = (lane & 3) * 2;
#pragma unroll
    for (int mi = 0; mi < 4; mi++) {
#pragma unroll
        for (int nj = 0; nj < 8; nj++) {
            int r0 = mrow + wm * 64 + mi * 16 + er;
            int cc = ncol + wn * 64 + nj * 8 + ec;
            float2 v0 = make_float2(acc[mi][nj][0], acc[mi][nj][1]);
            float2 v1 = make_float2(acc[mi][nj][2], acc[mi][nj][3]);
            if (EPI == 1) {
                float b0 = bias[cc], b1 = bias[cc + 1];
                v0.x += b0; v0.y += b1; v1.x += b0; v1.y += b1;
                v0.x = (v0.x > 20.f) ? v0.x : log1pf(__expf(v0.x));
                v0.y = (v0.y > 20.f) ? v0.y : log1pf(__expf(v0.y));
                v1.x = (v1.x > 20.f) ? v1.x : log1pf(__expf(v1.x));
                v1.y = (v1.y > 20.f) ? v1.y : log1pf(__expf(v1.y));
            }
            *reinterpret_cast<float2*>(C + (size_t)r0 * ldc + cc) = v0;
            *reinterpret_cast<float2*>(C + (size_t)(r0 + 8) * ldc + cc) = v1;
        }
    }
}

// ---------------------------------------------------------------------------
// Merged fp32 -> (bf16 hi, lo) conversions
// ---------------------------------------------------------------------------
#define CVT_N1 (M_ROWS * DMODEL / 4)
#define CVT_N2 (XZ_COLS * DMODEL / 4)
#define CVT_N3 (DMODEL * DINNER / 4)
#define CVT_N4 (XDBL_COLS * DINNER / 4)
#define CVT_N5 (DINNER * DTRANK / 4)

__global__ void cvt_all_kernel(const float* __restrict__ x,
                               const float* __restrict__ wi,
                               const float* __restrict__ wo,
                               const float* __restrict__ xw,
                               const float* __restrict__ dw)
{
    int i = blockIdx.x * blockDim.x + threadIdx.x;
    const float* src; __nv_bfloat16 *hi, *lo; int off;
    if (i < CVT_N1)                         { src = x;  hi = g_xhi;  lo = g_xlo;  off = i; }
    else if (i < CVT_N1+CVT_N2)             { src = wi; hi = g_wihi; lo = g_wilo; off = i - CVT_N1; }
    else if (i < CVT_N1+CVT_N2+CVT_N3)      { src = wo; hi = g_wohi; lo = g_wolo; off = i - CVT_N1 - CVT_N2; }
    else if (i < CVT_N1+CVT_N2+CVT_N3+CVT_N4) { src = xw; hi = g_xwhi; lo = g_xwlo; off = i - CVT_N1 - CVT_N2 - CVT_N3; }
    else if (i < CVT_N1+CVT_N2+CVT_N3+CVT_N4+CVT_N5) { src = dw; hi = g_dwhi; lo = g_dwlo; off = i - CVT_N1 - CVT_N2 - CVT_N3 - CVT_N4; }
    else return;

    float4 v = reinterpret_cast<const float4*>(src)[off];
    uint2 ho, lo2;
    split_bf16x4(v, ho, lo2);
    reinterpret_cast<uint2*>(hi)[off] = ho;
    reinterpret_cast<uint2*>(lo)[off] = lo2;
}

// ---------------------------------------------------------------------------
// Depthwise causal conv1d + bias + SiLU; also emits bf16 hi/lo of xc.
// ---------------------------------------------------------------------------
__global__ void conv_silu_kernel(const float* __restrict__ conv_w,
                                 const float* __restrict__ conv_b)
{
    int idx = blockIdx.x * blockDim.x + threadIdx.x;
    if (idx >= M_ROWS * DINNER / 4) return;
    int d4 = (idx % (DINNER / 4)) * 4;
    int m  = idx / (DINNER / 4);
    int t  = m % LSEQ;
    int b  = m / LSEQ;

    float4 acc = *reinterpret_cast<const float4*>(conv_b + d4);
#pragma unroll
    for (int j = 0; j < DCONV; j++) {
        int tt = t - (DCONV - 1) + j;
        if (tt >= 0) {
            float4 v = *reinterpret_cast<const float4*>(
                g_xz + (size_t)(b * LSEQ + tt) * XZ_COLS + d4);
            acc.x += v.x * __ldg(conv_w + (d4 + 0) * DCONV + j);
            acc.y += v.y * __ldg(conv_w + (d4 + 1) * DCONV + j);
            acc.z += v.z * __ldg(conv_w + (d4 + 2) * DCONV + j);
            acc.w += v.w * __ldg(conv_w + (d4 + 3) * DCONV + j);
        }
    }
    float4 o;
    o.x = acc.x / (1.f + __expf(-acc.x));
    o.y = acc.y / (1.f + __expf(-acc.y));
    o.z = acc.z / (1.f + __expf(-acc.z));
    o.w = acc.w / (1.f + __expf(-acc.w));
    size_t off = (size_t)m * DINNER + d4;
    *reinterpret_cast<float4*>(g_xc + off) = o;
    uint2 ho, lo2;
    split_bf16x4(o, ho, lo2);
    reinterpret_cast<uint2*>(g_xchi)[off / 4] = ho;
    reinterpret_cast<uint2*>(g_xclo)[off / 4] = lo2;
}

// ---------------------------------------------------------------------------
// x_proj reduce: sum partials -> g_xdbl; also emit dt-rank hi/lo for dt_proj.
// ---------------------------------------------------------------------------
__global__ void xproj_reduce_kernel()
{
    int i = blockIdx.x * blockDim.x + threadIdx.x;
    if (i >= M_ROWS * XDBL_COLS) return;
    int r = i / XDBL_COLS, c = i % XDBL_COLS;
    float s = 0.f;
#pragma unroll
    for (int z = 0; z < NSLICE; z++)
        s += g_xp2[(size_t)z * M_ROWS * XPN + (size_t)r * XPN + c];
    g_xdbl[i] = s;
    if (c < DTRANK) {
        __nv_bfloat16 h = __float2bfloat16(s);
        g_dthi[(size_t)r * DTRANK + c] = h;
        g_dtlo[(size_t)r * DTRANK + c] = __float2bfloat16(s - __bfloat162float(h));
    }
}

// ---------------------------------------------------------------------------
// Chunked selective scan (pass1 / combine / pass2), NCHUNK=16
// ---------------------------------------------------------------------------
__global__ void scan_pass1(const float* __restrict__ A_log)
{
    const int lane16 = threadIdx.x & 15;
    const int grp    = threadIdx.x >> 4;
    const int b      = blockIdx.x / (DINNER / 16);
    const int d      = (blockIdx.x % (DINNER / 16)) * 16 + grp;
    const int ck     = blockIdx.y;
    const int t0     = ck * CLEN;

    const float Ad = -__expf(A_log[d * DSTATE + lane16]);

    const float* dt_p = g_dt   + ((size_t)b * LSEQ + t0) * DINNER + d;
    const float* x_p  = g_xc   + ((size_t)b * LSEQ + t0) * DINNER + d;
    const float* bc_p = g_xdbl + ((size_t)b * LSEQ + t0) * XDBL_COLS;

    float h = 0.f, p = 1.f;
    float d0 = dt_p[0], x0 = x_p[0];
    float B0 = bc_p[DTRANK + lane16];
    float d1 = dt_p[DINNER], x1 = x_p[DINNER];
    float B1 = bc_p[XDBL_COLS + DTRANK + lane16];

    for (int t = 0; t < CLEN; t++) {
        float d2 = 0.f, x2 = 0.f, B2 = 0.f;
        if (t + 2 < CLEN) {
            d2 = dt_p[(size_t)(t + 2) * DINNER];
            x2 = x_p [(size_t)(t + 2) * DINNER];
            B2 = bc_p[(size_t)(t + 2) * XDBL_COLS + DTRANK + lane16];
        }
        float dA = __expf(d0 * Ad);
        h = dA * h + (d0 * x0) * B0;
        p *= dA;
        d0 = d1; x0 = x1; B0 = B1;
        d1 = d2; x1 = x2; B1 = B2;
    }
    size_t idx = (((size_t)b * DINNER + d) * DSTATE + lane16) * NCHUNK + ck;
    g_P[idx] = p;
    g_S[idx] = h;
}

__global__ void scan_combine()
{
    int i = blockIdx.x * blockDim.x + threadIdx.x;
    if (i >= B_SZ * DINNER * DSTATE) return;
    size_t base = (size_t)i * NCHUNK;
    float h = 0.f;
#pragma unroll
    for (int c = 0; c < NCHUNK; c++) {
        g_h0[base + c] = h;
        h = g_S[base + c] + g_P[base + c] * h;
    }
}

__global__ void scan_pass2(const float* __restrict__ A_log,
                           const float* __restrict__ D_param)
{
    const int lane16 = threadIdx.x & 15;
    const int grp    = threadIdx.x >> 4;
    const int b      = blockIdx.x / (DINNER / 16);
    const int d      = (blockIdx.x % (DINNER / 16)) * 16 + grp;
    const int ck     = blockIdx.y;
    const int t0     = ck * CLEN;

    const float Ad = -__expf(A_log[d * DSTATE + lane16]);
    const float Dd = D_param[d];

    const float* dt_p = g_dt   + ((size_t)b * LSEQ + t0) * DINNER + d;
    const float* x_p  = g_xc   + ((size_t)b * LSEQ + t0) * DINNER + d;
    const float* bc_p = g_xdbl + ((size_t)b * LSEQ + t0) * XDBL_COLS;
    float*       y_p  = g_y    + ((size_t)b * LSEQ + t0) * DINNER + d;

    float h = g_h0[(((size_t)b * DINNER + d) * DSTATE + lane16) * NCHUNK + ck];

    float d0 = dt_p[0], x0 = x_p[0];
    float B0 = bc_p[DTRANK + lane16];
    float C0 = bc_p[DTRANK + DSTATE + lane16];
    float d1 = dt_p[DINNER], x1 = x_p[DINNER];
    float B1 = bc_p[XDBL_COLS + DTRANK + lane16];
    float C1 = bc_p[XDBL_COLS + DTRANK + DSTATE + lane16];

    for (int t = 0; t < CLEN; t++) {
        float d2 = 0.f, x2 = 0.f, B2 = 0.f, C2 = 0.f;
        if (t + 2 < CLEN) {
            d2 = dt_p[(size_t)(t + 2) * DINNER];
            x2 = x_p [(size_t)(t + 2) * DINNER];
            B2 = bc_p[(size_t)(t + 2) * XDBL_COLS + DTRANK + lane16];
            C2 = bc_p[(size_t)(t + 2) * XDBL_COLS + DTRANK + DSTATE + lane16];
        }
        float dA = __expf(d0 * Ad);
        h = dA * h + (d0 * x0) * B0;
        float p = h * C0;
        p += __shfl_xor_sync(0xffffffffu, p, 1);
        p += __shfl_xor_sync(0xffffffffu, p, 2);
        p += __shfl_xor_sync(0xffffffffu, p, 4);
        p += __shfl_xor_sync(0xffffffffu, p, 8);
        if (lane16 == 0)
            y_p[(size_t)t * DINNER] = p + Dd * x0;
        d0 = d1; x0 = x1; B0 = B1; C0 = C1;
        d1 = d2; x1 = x2; B1 = B2; C1 = C2;
    }
}

// ---------------------------------------------------------------------------
// Gate + split-bf16 convert (coalesced, standalone)
// ---------------------------------------------------------------------------
__global__ void gate_cvt_kernel()
{
    int idx = blockIdx.x * blockDim.x + threadIdx.x;
    if (idx >= M_ROWS * DINNER / 4) return;
    int d4 = (idx % (DINNER / 4)) * 4;
    int m  = idx / (DINNER / 4);
    float4 z = *reinterpret_cast<const float4*>(g_xz + (size_t)m * XZ_COLS + DINNER + d4);
    float4 y = *reinterpret_cast<const float4*>(g_y + (size_t)m * DINNER + d4);
    float4 v;
    v.x = y.x * (z.x / (1.f + __expf(-z.x)));
    v.y = y.y * (z.y / (1.f + __expf(-z.y)));
    v.z = y.z * (z.z / (1.f + __expf(-z.z)));
    v.w = y.w * (z.w / (1.f + __expf(-z.w)));
    uint2 ho, lo2;
    split_bf16x4(v, ho, lo2);
    size_t off = ((size_t)m * DINNER + d4) / 4;
    reinterpret_cast<uint2*>(g_yhi)[off] = ho;
    reinterpret_cast<uint2*>(g_ylo)[off] = lo2;
}

// ---------------------------------------------------------------------------
// Launch
// ---------------------------------------------------------------------------
extern "C" void kernel_launch(void* const* d_in, const int* in_sizes, int n_in,
                              void* d_out, int out_size)
{
    const float* x         = (const float*)d_in[0];
    const float* in_proj_w = (const float*)d_in[1];
    const float* conv_w    = (const float*)d_in[2];
    const float* conv_b    = (const float*)d_in[3];
    const float* x_proj_w  = (const float*)d_in[4];
    const float* dt_proj_w = (const float*)d_in[5];
    const float* dt_proj_b = (const float*)d_in[6];
    const float* A_log     = (const float*)d_in[7];
    const float* D_param   = (const float*)d_in[8];
    const float* out_proj_w= (const float*)d_in[9];
    float* out = (float*)d_out;

    float *xz, *dt, *xp2;
    cudaGetSymbolAddress((void**)&xz,  g_xz);
    cudaGetSymbolAddress((void**)&dt,  g_dt);
    cudaGetSymbolAddress((void**)&xp2, g_xp2);
    __nv_bfloat16 *xhi, *xlo, *wihi, *wilo, *yhi, *ylo, *wohi, *wolo;
    __nv_bfloat16 *xchi, *xclo, *xwhi, *xwlo, *dthi, *dtlo, *dwhi, *dwlo;
    cudaGetSymbolAddress((void**)&xhi,  g_xhi);
    cudaGetSymbolAddress((void**)&xlo,  g_xlo);
    cudaGetSymbolAddress((void**)&wihi, g_wihi);
    cudaGetSymbolAddress((void**)&wilo, g_wilo);
    cudaGetSymbolAddress((void**)&yhi,  g_yhi);
    cudaGetSymbolAddress((void**)&ylo,  g_ylo);
    cudaGetSymbolAddress((void**)&wohi, g_wohi);
    cudaGetSymbolAddress((void**)&wolo, g_wolo);
    cudaGetSymbolAddress((void**)&xchi, g_xchi);
    cudaGetSymbolAddress((void**)&xclo, g_xclo);
    cudaGetSymbolAddress((void**)&xwhi, g_xwhi);
    cudaGetSymbolAddress((void**)&xwlo, g_xwlo);
    cudaGetSymbolAddress((void**)&dthi, g_dthi);
    cudaGetSymbolAddress((void**)&dtlo, g_dtlo);
    cudaGetSymbolAddress((void**)&dwhi, g_dwhi);
    cudaGetSymbolAddress((void**)&dwlo, g_dwlo);

    cudaFuncSetAttribute(tc_gemm_kernel<0>, cudaFuncAttributeMaxDynamicSharedMemorySize, TCSMEM);
    cudaFuncSetAttribute(tc_gemm_kernel<1>, cudaFuncAttributeMaxDynamicSharedMemorySize, TCSMEM);

    // 0) merged split-bf16 conversions
    {
        int n = CVT_N1 + CVT_N2 + CVT_N3 + CVT_N4 + CVT_N5;
        cvt_all_kernel<<<(n + 255) / 256, 256>>>(x, in_proj_w, out_proj_w, x_proj_w, dt_proj_w);
    }

    // 1) in_proj: xz = x * Wi^T
    {
        dim3 grid(XZ_COLS / TCBN, M_ROWS / TCBM, 1);
        tc_gemm_kernel<0><<<grid, 128, TCSMEM>>>(DMODEL, DMODEL,
            xhi, xlo, wihi, wilo, xz, XZ_COLS, 0, nullptr);
    }

    // 2) conv + silu (+ hi/lo emit)
    {
        int n = M_ROWS * DINNER / 4;
        conv_silu_kernel<<<(n + 255) / 256, 256>>>(conv_w, conv_b);
    }

    // 3) x_proj on tensor cores, split-K x4; then reduce (+ dt hi/lo emit)
    {
        dim3 grid(1, M_ROWS / TCBM, NSLICE);
        tc_gemm_kernel<0><<<grid, 128, TCSMEM>>>(DINNER, KSLICE,
            xchi, xclo, xwhi, xwlo, xp2, XPN, (size_t)M_ROWS * XPN, nullptr);
        int n = M_ROWS * XDBL_COLS;
        xproj_reduce_kernel<<<(n + 255) / 256, 256>>>();
    }

    // 4) dt_proj on tensor cores (K=64) + bias + softplus epilogue
    {
        dim3 grid(DINNER / TCBN, M_ROWS / TCBM, 1);
        tc_gemm_kernel<1><<<grid, 128, TCSMEM>>>(DTRANK, DTRANK,
            dthi, dtlo, dwhi, dwlo, dt, DINNER, 0, dt_proj_b);
    }

    // 5) chunked parallel scan (NCHUNK=16)
    {
        dim3 grid(B_SZ * DINNER / 16, NCHUNK);
        scan_pass1<<<grid, 256>>>(A_log);
        int n = B_SZ * DINNER * DSTATE;
        scan_combine<<<(n + 255) / 256, 256>>>();
        scan_pass2<<<grid, 256>>>(A_log, D_param);
    }

    // 6) gate + split convert
    {
        int n = M_ROWS * DINNER / 4;
        gate_cvt_kernel<<<(n + 255) / 256, 256>>>();
    }

    // 7) out_proj
    {
        dim3 grid(DMODEL / TCBN, M_ROWS / TCBM, 1);
        tc_gemm_kernel<0><<<grid, 128, TCSMEM>>>(DINNER, DINNER,
            yhi, ylo, wohi, wolo, out, DMODEL, 0, nullptr);
    }
}

// round 13
// speedup vs baseline: 1.4849x; 1.4420x over previous
#include <cuda_runtime.h>
#include <cuda_fp16.h>
#include <math.h>
#include <stdint.h>

// ---------------------------------------------------------------------------
// Problem constants
// ---------------------------------------------------------------------------
#define B_SZ    2
#define LSEQ    2048
#define DMODEL  1024
#define DINNER  2048
#define DSTATE  16
#define DTRANK  64
#define DCONV   4
#define M_ROWS  (B_SZ * LSEQ)            // 4096
#define XZ_COLS (2 * DINNER)             // 4096
#define XDBL_COLS (DTRANK + 2 * DSTATE)  // 96

#define NCHUNK  16
#define CLEN    (LSEQ / NCHUNK)          // 128
#define NSLICE  8
#define KSLICE  (DINNER / NSLICE)        // 256
#define XPN     128                      // padded N for x_proj tc-gemm

// ---------------------------------------------------------------------------
// Scratch
// ---------------------------------------------------------------------------
__device__ float g_xz  [(size_t)M_ROWS * XZ_COLS];
__device__ float g_xc  [(size_t)M_ROWS * DINNER];
__device__ float g_xdbl[(size_t)M_ROWS * XDBL_COLS];
__device__ float g_dt  [(size_t)M_ROWS * DINNER];
__device__ float g_y   [(size_t)M_ROWS * DINNER];
__device__ float g_xp2 [(size_t)NSLICE * M_ROWS * XPN];   // x_proj partials (padded)

__device__ float g_P [(size_t)B_SZ * DINNER * DSTATE * NCHUNK];
__device__ float g_S [(size_t)B_SZ * DINNER * DSTATE * NCHUNK];
__device__ float g_h0[(size_t)B_SZ * DINNER * DSTATE * NCHUNK];

// fp16 GEMM operands
__device__ __half g_xh [(size_t)M_ROWS * DMODEL];
__device__ __half g_wih[(size_t)XZ_COLS * DMODEL];
__device__ __half g_yh [(size_t)M_ROWS * DINNER];
__device__ __half g_woh[(size_t)DMODEL * DINNER];
__device__ __half g_xch[(size_t)M_ROWS * DINNER];
__device__ __half g_xwh[(size_t)XPN * DINNER];            // rows 96..127 stay zero
__device__ __half g_dth[(size_t)M_ROWS * DTRANK];
__device__ __half g_dwh[(size_t)DINNER * DTRANK];

// ---------------------------------------------------------------------------
// PTX helpers
// ---------------------------------------------------------------------------
__device__ __forceinline__ uint32_t smem_u32(const void* p) {
    uint32_t a;
    asm("{ .reg .u64 t; cvta.to.shared.u64 t, %1; cvt.u32.u64 %0, t; }" : "=r"(a) : "l"(p));
    return a;
}
__device__ __forceinline__ void cp_async16(uint32_t saddr, const void* gaddr) {
    asm volatile("cp.async.cg.shared.global [%0], [%1], 16;" :: "r"(saddr), "l"(gaddr));
}
#define CP_COMMIT()  asm volatile("cp.async.commit_group;" ::: "memory")
#define CP_WAIT1()   asm volatile("cp.async.wait_group 1;" ::: "memory")

__device__ __forceinline__ void ldsm_x4(uint32_t (&r)[4], uint32_t addr) {
    asm volatile("ldmatrix.sync.aligned.m8n8.x4.shared.b16 {%0,%1,%2,%3}, [%4];"
        : "=r"(r[0]), "=r"(r[1]), "=r"(r[2]), "=r"(r[3]) : "r"(addr));
}
__device__ __forceinline__ void mma_f16(float (&d)[4],
                                        const uint32_t (&a)[4],
                                        uint32_t b0, uint32_t b1) {
    asm volatile(
        "mma.sync.aligned.m16n8k16.row.col.f32.f16.f16.f32 "
        "{%0,%1,%2,%3}, {%4,%5,%6,%7}, {%8,%9}, {%0,%1,%2,%3};"
        : "+f"(d[0]), "+f"(d[1]), "+f"(d[2]), "+f"(d[3])
        : "r"(a[0]), "r"(a[1]), "r"(a[2]), "r"(a[3]), "r"(b0), "r"(b1));
}

__device__ __forceinline__ uint2 cvt_f16x4(float4 v) {
    __half2 h01 = __floats2half2_rn(v.x, v.y);
    __half2 h23 = __floats2half2_rn(v.z, v.w);
    uint2 o;
    o.x = *reinterpret_cast<uint32_t*>(&h01);
    o.y = *reinterpret_cast<uint32_t*>(&h23);
    return o;
}

// ---------------------------------------------------------------------------
// fp16 TC GEMM: C[M,N](+slice) = A[M,K-range]*B[N,K-range]^T  (single pass)
// 4-warp 128x128 tile, warp tile 64x64, 2-stage cp.async ring.
// ---------------------------------------------------------------------------
#define TCBM 128
#define TCBN 128
#define TCBK 32
#define PITCHB 80
#define OPTILE (TCBM * PITCHB)           // 10240 B
#define STAGEB (2 * OPTILE)              // 20480 B (A, B)
#define TCSMEM (2 * STAGEB)              // 40960 B

__device__ __forceinline__ void fill_op128(uint32_t sbase, const __half* g,
                                           int grow0, int lda, int k0, int tid) {
#pragma unroll
    for (int t = 0; t < 4; t++) {
        int u = tid + t * 128;
        int r = u >> 2, seg = u & 3;
        const __half* gp = g + (size_t)(grow0 + r) * lda + k0 + seg * 8;
        cp_async16(sbase + r * PITCHB + seg * 16, gp);
    }
}
__device__ __forceinline__ void fill_stage(uint32_t s, const __half* A,
                                           const __half* B,
                                           int mrow, int ncol, int lda, int k0, int tid) {
    fill_op128(s,          A, mrow, lda, k0, tid);
    fill_op128(s + OPTILE, B, ncol, lda, k0, tid);
}

template<int EPI>
__global__ void __launch_bounds__(128, 2)
tc_gemm_kernel(int lda, int klen,
               const __half* __restrict__ A, const __half* __restrict__ B,
               float* __restrict__ C, int ldc, size_t c_slice_stride,
               const float* __restrict__ bias)
{
    extern __shared__ char smem[];
    const uint32_t sb = smem_u32(smem);

    const int tid  = threadIdx.x;
    const int lane = tid & 31;
    const int w    = tid >> 5;
    const int wm   = w & 1;
    const int wn   = w >> 1;
    const int mrow = blockIdx.y * TCBM;
    const int ncol = blockIdx.x * TCBN;
    const int kbeg = blockIdx.z * klen;
    C += (size_t)blockIdx.z * c_slice_stride;

    float acc[4][8][4];
#pragma unroll
    for (int i = 0; i < 4; i++)
#pragma unroll
        for (int j = 0; j < 8; j++)
#pragma unroll
            for (int e = 0; e < 4; e++) acc[i][j][e] = 0.f;

    const int nc = klen / TCBK;

    fill_stage(sb, A, B, mrow, ncol, lda, kbeg, tid);
    CP_COMMIT();

    const int a_row = (lane & 15);
    const int a_cb  = (lane >> 4);
    const int b_row = (lane & 7) + ((lane >> 4) << 3);
    const int b_cb  = (lane >> 3) & 1;

    for (int c = 0; c < nc; c++) {
        if (c + 1 < nc) {
            fill_stage(sb + ((c + 1) & 1) * STAGEB, A, B,
                       mrow, ncol, lda, kbeg + (c + 1) * TCBK, tid);
        }
        CP_COMMIT();
        CP_WAIT1();
        __syncthreads();

        const uint32_t s  = sb + (c & 1) * STAGEB;
        const uint32_t sA = s;
        const uint32_t sB = s + OPTILE;

#pragma unroll
        for (int ks = 0; ks < 2; ks++) {
            uint32_t ah[4][4], bh[4][4];
#pragma unroll
            for (int mi = 0; mi < 4; mi++) {
                uint32_t ao = (uint32_t)((wm * 64 + mi * 16 + a_row) * PITCHB + ks * 32 + a_cb * 16);
                ldsm_x4(ah[mi], sA + ao);
            }
#pragma unroll
            for (int j = 0; j < 4; j++) {
                uint32_t bo = (uint32_t)((wn * 64 + j * 16 + b_row) * PITCHB + ks * 32 + b_cb * 16);
                ldsm_x4(bh[j], sB + bo);
            }
#pragma unroll
            for (int mi = 0; mi < 4; mi++)
#pragma unroll
                for (int nj = 0; nj < 8; nj++) {
                    const int j = nj >> 1, h = (nj & 1) * 2;
                    mma_f16(acc[mi][nj], ah[mi], bh[j][h], bh[j][h + 1]);
                }
        }
        __syncthreads();
    }

    const int er = lane >> 2;
    const int ec = (lane & 3) * 2;
#pragma unroll
    for (int mi = 0; mi < 4; mi++) {
#pragma unroll
        for (int nj = 0; nj < 8; nj++) {
            int r0 = mrow + wm * 64 + mi * 16 + er;
            int cc = ncol + wn * 64 + nj * 8 + ec;
            float2 v0 = make_float2(acc[mi][nj][0], acc[mi][nj][1]);
            float2 v1 = make_float2(acc[mi][nj][2], acc[mi][nj][3]);
            if (EPI == 1) {
                float b0 = bias[cc], b1 = bias[cc + 1];
                v0.x += b0; v0.y += b1; v1.x += b0; v1.y += b1;
                v0.x = (v0.x > 20.f) ? v0.x : log1pf(__expf(v0.x));
                v0.y = (v0.y > 20.f) ? v0.y : log1pf(__expf(v0.y));
                v1.x = (v1.x > 20.f) ? v1.x : log1pf(__expf(v1.x));
                v1.y = (v1.y > 20.f) ? v1.y : log1pf(__expf(v1.y));
            }
            *reinterpret_cast<float2*>(C + (size_t)r0 * ldc + cc) = v0;
            *reinterpret_cast<float2*>(C + (size_t)(r0 + 8) * ldc + cc) = v1;
        }
    }
}

// ---------------------------------------------------------------------------
// Merged fp32 -> fp16 conversions: x, in_proj_w, out_proj_w, x_proj_w, dt_proj_w
// ---------------------------------------------------------------------------
#define CVT_N1 (M_ROWS * DMODEL / 4)
#define CVT_N2 (XZ_COLS * DMODEL / 4)
#define CVT_N3 (DMODEL * DINNER / 4)
#define CVT_N4 (XDBL_COLS * DINNER / 4)
#define CVT_N5 (DINNER * DTRANK / 4)

__global__ void cvt_all_kernel(const float* __restrict__ x,
                               const float* __restrict__ wi,
                               const float* __restrict__ wo,
                               const float* __restrict__ xw,
                               const float* __restrict__ dw)
{
    int i = blockIdx.x * blockDim.x + threadIdx.x;
    const float* src; __half* dst; int off;
    if (i < CVT_N1)                           { src = x;  dst = g_xh;  off = i; }
    else if (i < CVT_N1+CVT_N2)               { src = wi; dst = g_wih; off = i - CVT_N1; }
    else if (i < CVT_N1+CVT_N2+CVT_N3)        { src = wo; dst = g_woh; off = i - CVT_N1 - CVT_N2; }
    else if (i < CVT_N1+CVT_N2+CVT_N3+CVT_N4) { src = xw; dst = g_xwh; off = i - CVT_N1 - CVT_N2 - CVT_N3; }
    else if (i < CVT_N1+CVT_N2+CVT_N3+CVT_N4+CVT_N5) { src = dw; dst = g_dwh; off = i - CVT_N1 - CVT_N2 - CVT_N3 - CVT_N4; }
    else return;

    float4 v = reinterpret_cast<const float4*>(src)[off];
    reinterpret_cast<uint2*>(dst)[off] = cvt_f16x4(v);
}

// ---------------------------------------------------------------------------
// Depthwise causal conv1d + bias + SiLU; also emits fp16 xc.
// ---------------------------------------------------------------------------
__global__ void conv_silu_kernel(const float* __restrict__ conv_w,
                                 const float* __restrict__ conv_b)
{
    int idx = blockIdx.x * blockDim.x + threadIdx.x;
    if (idx >= M_ROWS * DINNER / 4) return;
    int d4 = (idx % (DINNER / 4)) * 4;
    int m  = idx / (DINNER / 4);
    int t  = m % LSEQ;
    int b  = m / LSEQ;

    float4 acc = *reinterpret_cast<const float4*>(conv_b + d4);
#pragma unroll
    for (int j = 0; j < DCONV; j++) {
        int tt = t - (DCONV - 1) + j;
        if (tt >= 0) {
            float4 v = *reinterpret_cast<const float4*>(
                g_xz + (size_t)(b * LSEQ + tt) * XZ_COLS + d4);
            acc.x += v.x * __ldg(conv_w + (d4 + 0) * DCONV + j);
            acc.y += v.y * __ldg(conv_w + (d4 + 1) * DCONV + j);
            acc.z += v.z * __ldg(conv_w + (d4 + 2) * DCONV + j);
            acc.w += v.w * __ldg(conv_w + (d4 + 3) * DCONV + j);
        }
    }
    float4 o;
    o.x = acc.x / (1.f + __expf(-acc.x));
    o.y = acc.y / (1.f + __expf(-acc.y));
    o.z = acc.z / (1.f + __expf(-acc.z));
    o.w = acc.w / (1.f + __expf(-acc.w));
    size_t off = (size_t)m * DINNER + d4;
    *reinterpret_cast<float4*>(g_xc + off) = o;
    reinterpret_cast<uint2*>(g_xch)[off / 4] = cvt_f16x4(o);
}

// ---------------------------------------------------------------------------
// x_proj reduce: sum partials -> g_xdbl; also emit fp16 dt-rank cols.
// ---------------------------------------------------------------------------
__global__ void xproj_reduce_kernel()
{
    int i = blockIdx.x * blockDim.x + threadIdx.x;
    if (i >= M_ROWS * XDBL_COLS) return;
    int r = i / XDBL_COLS, c = i % XDBL_COLS;
    float s = 0.f;
#pragma unroll
    for (int z = 0; z < NSLICE; z++)
        s += g_xp2[(size_t)z * M_ROWS * XPN + (size_t)r * XPN + c];
    g_xdbl[i] = s;
    if (c < DTRANK)
        g_dth[(size_t)r * DTRANK + c] = __float2half_rn(s);
}

// ---------------------------------------------------------------------------
// Chunked selective scan (pass1 / combine / pass2)
// ---------------------------------------------------------------------------
__global__ void scan_pass1(const float* __restrict__ A_log)
{
    const int lane16 = threadIdx.x & 15;
    const int grp    = threadIdx.x >> 4;
    const int b      = blockIdx.x / (DINNER / 16);
    const int d      = (blockIdx.x % (DINNER / 16)) * 16 + grp;
    const int ck     = blockIdx.y;
    const int t0     = ck * CLEN;

    const float Ad = -__expf(A_log[d * DSTATE + lane16]);

    const float* dt_p = g_dt   + ((size_t)b * LSEQ + t0) * DINNER + d;
    const float* x_p  = g_xc   + ((size_t)b * LSEQ + t0) * DINNER + d;
    const float* bc_p = g_xdbl + ((size_t)b * LSEQ + t0) * XDBL_COLS;

    float h = 0.f, p = 1.f;
    float d0 = dt_p[0], x0 = x_p[0];
    float B0 = bc_p[DTRANK + lane16];
    float d1 = dt_p[DINNER], x1 = x_p[DINNER];
    float B1 = bc_p[XDBL_COLS + DTRANK + lane16];

    for (int t = 0; t < CLEN; t++) {
        float d2 = 0.f, x2 = 0.f, B2 = 0.f;
        if (t + 2 < CLEN) {
            d2 = dt_p[(size_t)(t + 2) * DINNER];
            x2 = x_p [(size_t)(t + 2) * DINNER];
            B2 = bc_p[(size_t)(t + 2) * XDBL_COLS + DTRANK + lane16];
        }
        float dA = __expf(d0 * Ad);
        h = dA * h + (d0 * x0) * B0;
        p *= dA;
        d0 = d1; x0 = x1; B0 = B1;
        d1 = d2; x1 = x2; B1 = B2;
    }
    size_t idx = (((size_t)b * DINNER + d) * DSTATE + lane16) * NCHUNK + ck;
    g_P[idx] = p;
    g_S[idx] = h;
}

__global__ void scan_combine()
{
    int i = blockIdx.x * blockDim.x + threadIdx.x;
    if (i >= B_SZ * DINNER * DSTATE) return;
    size_t base = (size_t)i * NCHUNK;
    float h = 0.f;
#pragma unroll
    for (int c = 0; c < NCHUNK; c++) {
        g_h0[base + c] = h;
        h = g_S[base + c] + g_P[base + c] * h;
    }
}

__global__ void scan_pass2(const float* __restrict__ A_log,
                           const float* __restrict__ D_param)
{
    const int lane16 = threadIdx.x & 15;
    const int grp    = threadIdx.x >> 4;
    const int b      = blockIdx.x / (DINNER / 16);
    const int d      = (blockIdx.x % (DINNER / 16)) * 16 + grp;
    const int ck     = blockIdx.y;
    const int t0     = ck * CLEN;

    const float Ad = -__expf(A_log[d * DSTATE + lane16]);
    const float Dd = D_param[d];

    const float* dt_p = g_dt   + ((size_t)b * LSEQ + t0) * DINNER + d;
    const float* x_p  = g_xc   + ((size_t)b * LSEQ + t0) * DINNER + d;
    const float* bc_p = g_xdbl + ((size_t)b * LSEQ + t0) * XDBL_COLS;
    float*       y_p  = g_y    + ((size_t)b * LSEQ + t0) * DINNER + d;

    float h = g_h0[(((size_t)b * DINNER + d) * DSTATE + lane16) * NCHUNK + ck];

    float d0 = dt_p[0], x0 = x_p[0];
    float B0 = bc_p[DTRANK + lane16];
    float C0 = bc_p[DTRANK + DSTATE + lane16];
    float d1 = dt_p[DINNER], x1 = x_p[DINNER];
    float B1 = bc_p[XDBL_COLS + DTRANK + lane16];
    float C1 = bc_p[XDBL_COLS + DTRANK + DSTATE + lane16];

    for (int t = 0; t < CLEN; t++) {
        float d2 = 0.f, x2 = 0.f, B2 = 0.f, C2 = 0.f;
        if (t + 2 < CLEN) {
            d2 = dt_p[(size_t)(t + 2) * DINNER];
            x2 = x_p [(size_t)(t + 2) * DINNER];
            B2 = bc_p[(size_t)(t + 2) * XDBL_COLS + DTRANK + lane16];
            C2 = bc_p[(size_t)(t + 2) * XDBL_COLS + DTRANK + DSTATE + lane16];
        }
        float dA = __expf(d0 * Ad);
        h = dA * h + (d0 * x0) * B0;
        float p = h * C0;
        p += __shfl_xor_sync(0xffffffffu, p, 1);
        p += __shfl_xor_sync(0xffffffffu, p, 2);
        p += __shfl_xor_sync(0xffffffffu, p, 4);
        p += __shfl_xor_sync(0xffffffffu, p, 8);
        if (lane16 == 0)
            y_p[(size_t)t * DINNER] = p + Dd * x0;
        d0 = d1; x0 = x1; B0 = B1; C0 = C1;
        d1 = d2; x1 = x2; B1 = B2; C1 = C2;
    }
}

// ---------------------------------------------------------------------------
// Gate + fp16 convert (coalesced, standalone)
// ---------------------------------------------------------------------------
__global__ void gate_cvt_kernel()
{
    int idx = blockIdx.x * blockDim.x + threadIdx.x;
    if (idx >= M_ROWS * DINNER / 4) return;
    int d4 = (idx % (DINNER / 4)) * 4;
    int m  = idx / (DINNER / 4);
    float4 z = *reinterpret_cast<const float4*>(g_xz + (size_t)m * XZ_COLS + DINNER + d4);
    float4 y = *reinterpret_cast<const float4*>(g_y + (size_t)m * DINNER + d4);
    float4 v;
    v.x = y.x * (z.x / (1.f + __expf(-z.x)));
    v.y = y.y * (z.y / (1.f + __expf(-z.y)));
    v.z = y.z * (z.z / (1.f + __expf(-z.z)));
    v.w = y.w * (z.w / (1.f + __expf(-z.w)));
    size_t off = ((size_t)m * DINNER + d4) / 4;
    reinterpret_cast<uint2*>(g_yh)[off] = cvt_f16x4(v);
}

// ---------------------------------------------------------------------------
// Launch
// ---------------------------------------------------------------------------
extern "C" void kernel_launch(void* const* d_in, const int* in_sizes, int n_in,
                              void* d_out, int out_size)
{
    const float* x         = (const float*)d_in[0];
    const float* in_proj_w = (const float*)d_in[1];
    const float* conv_w    = (const float*)d_in[2];
    const float* conv_b    = (const float*)d_in[3];
    const float* x_proj_w  = (const float*)d_in[4];
    const float* dt_proj_w = (const float*)d_in[5];
    const float* dt_proj_b = (const float*)d_in[6];
    const float* A_log     = (const float*)d_in[7];
    const float* D_param   = (const float*)d_in[8];
    const float* out_proj_w= (const float*)d_in[9];
    float* out = (float*)d_out;

    float *xz, *dt, *xp2;
    cudaGetSymbolAddress((void**)&xz,  g_xz);
    cudaGetSymbolAddress((void**)&dt,  g_dt);
    cudaGetSymbolAddress((void**)&xp2, g_xp2);
    __half *xh, *wih, *yh, *woh, *xch, *xwh, *dth, *dwh;
    cudaGetSymbolAddress((void**)&xh,  g_xh);
    cudaGetSymbolAddress((void**)&wih, g_wih);
    cudaGetSymbolAddress((void**)&yh,  g_yh);
    cudaGetSymbolAddress((void**)&woh, g_woh);
    cudaGetSymbolAddress((void**)&xch, g_xch);
    cudaGetSymbolAddress((void**)&xwh, g_xwh);
    cudaGetSymbolAddress((void**)&dth, g_dth);
    cudaGetSymbolAddress((void**)&dwh, g_dwh);

    cudaFuncSetAttribute(tc_gemm_kernel<0>, cudaFuncAttributeMaxDynamicSharedMemorySize, TCSMEM);
    cudaFuncSetAttribute(tc_gemm_kernel<1>, cudaFuncAttributeMaxDynamicSharedMemorySize, TCSMEM);

    // 0) merged fp32 -> fp16 conversions
    {
        int n = CVT_N1 + CVT_N2 + CVT_N3 + CVT_N4 + CVT_N5;
        cvt_all_kernel<<<(n + 255) / 256, 256>>>(x, in_proj_w, out_proj_w, x_proj_w, dt_proj_w);
    }

    // 1) in_proj: xz = x * Wi^T
    {
        dim3 grid(XZ_COLS / TCBN, M_ROWS / TCBM, 1);
        tc_gemm_kernel<0><<<grid, 128, TCSMEM>>>(DMODEL, DMODEL,
            xh, wih, xz, XZ_COLS, 0, nullptr);
    }

    // 2) conv + silu (+ fp16 emit)
    {
        int n = M_ROWS * DINNER / 4;
        conv_silu_kernel<<<(n + 255) / 256, 256>>>(conv_w, conv_b);
    }

    // 3) x_proj on tensor cores, split-K x8; then reduce (+ fp16 dt emit)
    {
        dim3 grid(1, M_ROWS / TCBM, NSLICE);
        tc_gemm_kernel<0><<<grid, 128, TCSMEM>>>(DINNER, KSLICE,
            xch, xwh, xp2, XPN, (size_t)M_ROWS * XPN, nullptr);
        int n = M_ROWS * XDBL_COLS;
        xproj_reduce_kernel<<<(n + 255) / 256, 256>>>();
    }

    // 4) dt_proj on tensor cores (K=64) + bias + softplus epilogue
    {
        dim3 grid(DINNER / TCBN, M_ROWS / TCBM, 1);
        tc_gemm_kernel<1><<<grid, 128, TCSMEM>>>(DTRANK, DTRANK,
            dth, dwh, dt, DINNER, 0, dt_proj_b);
    }

    // 5) chunked parallel scan (NCHUNK=16)
    {
        dim3 grid(B_SZ * DINNER / 16, NCHUNK);
        scan_pass1<<<grid, 256>>>(A_log);
        int n = B_SZ * DINNER * DSTATE;
        scan_combine<<<(n + 255) / 256, 256>>>();
        scan_pass2<<<grid, 256>>>(A_log, D_param);
    }

    // 6) gate + fp16 convert
    {
        int n = M_ROWS * DINNER / 4;
        gate_cvt_kernel<<<(n + 255) / 256, 256>>>();
    }

    // 7) out_proj
    {
        dim3 grid(DMODEL / TCBN, M_ROWS / TCBM, 1);
        tc_gemm_kernel<0><<<grid, 128, TCSMEM>>>(DINNER, DINNER,
            yh, woh, out, DMODEL, 0, nullptr);
    }
}

// round 15
// speedup vs baseline: 1.4935x; 1.0058x over previous
#include <cuda_runtime.h>
#include <cuda_fp16.h>
#include <math.h>
#include <stdint.h>

// ---------------------------------------------------------------------------
// Problem constants
// ---------------------------------------------------------------------------
#define B_SZ    2
#define LSEQ    2048
#define DMODEL  1024
#define DINNER  2048
#define DSTATE  16
#define DTRANK  64
#define DCONV   4
#define M_ROWS  (B_SZ * LSEQ)            // 4096
#define XZ_COLS (2 * DINNER)             // 4096
#define XDBL_COLS (DTRANK + 2 * DSTATE)  // 96

#define NCHUNK  16
#define CLEN    (LSEQ / NCHUNK)          // 128
#define NSLICE  8
#define KSLICE  (DINNER / NSLICE)        // 256
#define XPN     128                      // padded N for x_proj tc-gemm

// ---------------------------------------------------------------------------
// Scratch
// ---------------------------------------------------------------------------
__device__ float g_xz  [(size_t)M_ROWS * XZ_COLS];
__device__ float g_xc  [(size_t)M_ROWS * DINNER];
__device__ float g_xdbl[(size_t)M_ROWS * XDBL_COLS];
__device__ float g_dt  [(size_t)M_ROWS * DINNER];
__device__ float g_y   [(size_t)M_ROWS * DINNER];
__device__ float g_xp2 [(size_t)NSLICE * M_ROWS * XPN];   // x_proj partials (padded)

__device__ float g_P [(size_t)B_SZ * DINNER * DSTATE * NCHUNK];
__device__ float g_S [(size_t)B_SZ * DINNER * DSTATE * NCHUNK];
__device__ float g_h0[(size_t)B_SZ * DINNER * DSTATE * NCHUNK];

// fp16 GEMM operands
__device__ __half g_xh [(size_t)M_ROWS * DMODEL];
__device__ __half g_wih[(size_t)XZ_COLS * DMODEL];
__device__ __half g_yh [(size_t)M_ROWS * DINNER];
__device__ __half g_woh[(size_t)DMODEL * DINNER];
__device__ __half g_xch[(size_t)M_ROWS * DINNER];
__device__ __half g_xwh[(size_t)XPN * DINNER];            // rows 96..127 stay zero
__device__ __half g_dth[(size_t)M_ROWS * DTRANK];
__device__ __half g_dwh[(size_t)DINNER * DTRANK];

// ---------------------------------------------------------------------------
// PTX helpers
// ---------------------------------------------------------------------------
__device__ __forceinline__ uint32_t smem_u32(const void* p) {
    uint32_t a;
    asm("{ .reg .u64 t; cvta.to.shared.u64 t, %1; cvt.u32.u64 %0, t; }" : "=r"(a) : "l"(p));
    return a;
}
__device__ __forceinline__ void cp_async16(uint32_t saddr, const void* gaddr) {
    asm volatile("cp.async.cg.shared.global [%0], [%1], 16;" :: "r"(saddr), "l"(gaddr));
}
#define CP_COMMIT()  asm volatile("cp.async.commit_group;" ::: "memory")
#define CP_WAIT1()   asm volatile("cp.async.wait_group 1;" ::: "memory")

__device__ __forceinline__ void ldsm_x4(uint32_t (&r)[4], uint32_t addr) {
    asm volatile("ldmatrix.sync.aligned.m8n8.x4.shared.b16 {%0,%1,%2,%3}, [%4];"
        : "=r"(r[0]), "=r"(r[1]), "=r"(r[2]), "=r"(r[3]) : "r"(addr));
}
__device__ __forceinline__ void mma_f16(float (&d)[4],
                                        const uint32_t (&a)[4],
                                        uint32_t b0, uint32_t b1) {
    asm volatile(
        "mma.sync.aligned.m16n8k16.row.col.f32.f16.f16.f32 "
        "{%0,%1,%2,%3}, {%4,%5,%6,%7}, {%8,%9}, {%0,%1,%2,%3};"
        : "+f"(d[0]), "+f"(d[1]), "+f"(d[2]), "+f"(d[3])
        : "r"(a[0]), "r"(a[1]), "r"(a[2]), "r"(a[3]), "r"(b0), "r"(b1));
}

__device__ __forceinline__ uint2 cvt_f16x4(float4 v) {
    __half2 h01 = __floats2half2_rn(v.x, v.y);
    __half2 h23 = __floats2half2_rn(v.z, v.w);
    uint2 o;
    o.x = *reinterpret_cast<uint32_t*>(&h01);
    o.y = *reinterpret_cast<uint32_t*>(&h23);
    return o;
}

// ---------------------------------------------------------------------------
// fp16 TC GEMM: C[M,N](+slice) = A[M,K-range]*B[N,K-range]^T  (single pass)
// 4-warp 128x128 tile, warp tile 64x64, BK=64, 2-stage cp.async ring.
// ---------------------------------------------------------------------------
#define TCBM 128
#define TCBN 128
#define TCBK 64
#define PITCHB 144                        // 128B data + 16B pad
#define OPTILE (TCBM * PITCHB)            // 18432 B
#define STAGEB (2 * OPTILE)               // 36864 B (A, B)
#define TCSMEM (2 * STAGEB)               // 73728 B

__device__ __forceinline__ void fill_op128(uint32_t sbase, const __half* g,
                                           int grow0, int lda, int k0, int tid) {
#pragma unroll
    for (int t = 0; t < 8; t++) {
        int u = tid + t * 128;            // 1024 chunks of 16B
        int r = u >> 3, seg = u & 7;
        const __half* gp = g + (size_t)(grow0 + r) * lda + k0 + seg * 8;
        cp_async16(sbase + r * PITCHB + seg * 16, gp);
    }
}
__device__ __forceinline__ void fill_stage(uint32_t s, const __half* A,
                                           const __half* B,
                                           int mrow, int ncol, int lda, int k0, int tid) {
    fill_op128(s,          A, mrow, lda, k0, tid);
    fill_op128(s + OPTILE, B, ncol, lda, k0, tid);
}

template<int EPI>
__global__ void __launch_bounds__(128, 2)
tc_gemm_kernel(int lda, int klen,
               const __half* __restrict__ A, const __half* __restrict__ B,
               float* __restrict__ C, int ldc, size_t c_slice_stride,
               const float* __restrict__ bias)
{
    extern __shared__ char smem[];
    const uint32_t sb = smem_u32(smem);

    const int tid  = threadIdx.x;
    const int lane = tid & 31;
    const int w    = tid >> 5;
    const int wm   = w & 1;
    const int wn   = w >> 1;
    const int mrow = blockIdx.y * TCBM;
    const int ncol = blockIdx.x * TCBN;
    const int kbeg = blockIdx.z * klen;
    C += (size_t)blockIdx.z * c_slice_stride;

    float acc[4][8][4];
#pragma unroll
    for (int i = 0; i < 4; i++)
#pragma unroll
        for (int j = 0; j < 8; j++)
#pragma unroll
            for (int e = 0; e < 4; e++) acc[i][j][e] = 0.f;

    const int nc = klen / TCBK;

    fill_stage(sb, A, B, mrow, ncol, lda, kbeg, tid);
    CP_COMMIT();

    const int a_row = (lane & 15);
    const int a_cb  = (lane >> 4);
    const int b_row = (lane & 7) + ((lane >> 4) << 3);
    const int b_cb  = (lane >> 3) & 1;

    for (int c = 0; c < nc; c++) {
        if (c + 1 < nc) {
            fill_stage(sb + ((c + 1) & 1) * STAGEB, A, B,
                       mrow, ncol, lda, kbeg + (c + 1) * TCBK, tid);
        }
        CP_COMMIT();
        CP_WAIT1();
        __syncthreads();

        const uint32_t s  = sb + (c & 1) * STAGEB;
        const uint32_t sA = s;
        const uint32_t sB = s + OPTILE;

#pragma unroll
        for (int ks = 0; ks < 4; ks++) {
            uint32_t ah[4][4], bh[4][4];
#pragma unroll
            for (int mi = 0; mi < 4; mi++) {
                uint32_t ao = (uint32_t)((wm * 64 + mi * 16 + a_row) * PITCHB + ks * 32 + a_cb * 16);
                ldsm_x4(ah[mi], sA + ao);
            }
#pragma unroll
            for (int j = 0; j < 4; j++) {
                uint32_t bo = (uint32_t)((wn * 64 + j * 16 + b_row) * PITCHB + ks * 32 + b_cb * 16);
                ldsm_x4(bh[j], sB + bo);
            }
#pragma unroll
            for (int mi = 0; mi < 4; mi++)
#pragma unroll
                for (int nj = 0; nj < 8; nj++) {
                    const int j = nj >> 1, h = (nj & 1) * 2;
                    mma_f16(acc[mi][nj], ah[mi], bh[j][h], bh[j][h + 1]);
                }
        }
        __syncthreads();
    }

    const int er = lane >> 2;
    const int ec = (lane & 3) * 2;
#pragma unroll
    for (int mi = 0; mi < 4; mi++) {
#pragma unroll
        for (int nj = 0; nj < 8; nj++) {
            int r0 = mrow + wm * 64 + mi * 16 + er;
            int cc = ncol + wn * 64 + nj * 8 + ec;
            float2 v0 = make_float2(acc[mi][nj][0], acc[mi][nj][1]);
            float2 v1 = make_float2(acc[mi][nj][2], acc[mi][nj][3]);
            if (EPI == 1) {
                float b0 = bias[cc], b1 = bias[cc + 1];
                v0.x += b0; v0.y += b1; v1.x += b0; v1.y += b1;
                v0.x = (v0.x > 20.f) ? v0.x : log1pf(__expf(v0.x));
                v0.y = (v0.y > 20.f) ? v0.y : log1pf(__expf(v0.y));
                v1.x = (v1.x > 20.f) ? v1.x : log1pf(__expf(v1.x));
                v1.y = (v1.y > 20.f) ? v1.y : log1pf(__expf(v1.y));
            }
            *reinterpret_cast<float2*>(C + (size_t)r0 * ldc + cc) = v0;
            *reinterpret_cast<float2*>(C + (size_t)(r0 + 8) * ldc + cc) = v1;
        }
    }
}

// ---------------------------------------------------------------------------
// Merged fp32 -> fp16 conversions: x, in_proj_w, out_proj_w, x_proj_w, dt_proj_w
// ---------------------------------------------------------------------------
#define CVT_N1 (M_ROWS * DMODEL / 4)
#define CVT_N2 (XZ_COLS * DMODEL / 4)
#define CVT_N3 (DMODEL * DINNER / 4)
#define CVT_N4 (XDBL_COLS * DINNER / 4)
#define CVT_N5 (DINNER * DTRANK / 4)

__global__ void cvt_all_kernel(const float* __restrict__ x,
                               const float* __restrict__ wi,
                               const float* __restrict__ wo,
                               const float* __restrict__ xw,
                               const float* __restrict__ dw)
{
    int i = blockIdx.x * blockDim.x + threadIdx.x;
    const float* src; __half* dst; int off;
    if (i < CVT_N1)                           { src = x;  dst = g_xh;  off = i; }
    else if (i < CVT_N1+CVT_N2)               { src = wi; dst = g_wih; off = i - CVT_N1; }
    else if (i < CVT_N1+CVT_N2+CVT_N3)        { src = wo; dst = g_woh; off = i - CVT_N1 - CVT_N2; }
    else if (i < CVT_N1+CVT_N2+CVT_N3+CVT_N4) { src = xw; dst = g_xwh; off = i - CVT_N1 - CVT_N2 - CVT_N3; }
    else if (i < CVT_N1+CVT_N2+CVT_N3+CVT_N4+CVT_N5) { src = dw; dst = g_dwh; off = i - CVT_N1 - CVT_N2 - CVT_N3 - CVT_N4; }
    else return;

    float4 v = reinterpret_cast<const float4*>(src)[off];
    reinterpret_cast<uint2*>(dst)[off] = cvt_f16x4(v);
}

// ---------------------------------------------------------------------------
// Depthwise causal conv1d + bias + SiLU; also emits fp16 xc.
// ---------------------------------------------------------------------------
__global__ void conv_silu_kernel(const float* __restrict__ conv_w,
                                 const float* __restrict__ conv_b)
{
    int idx = blockIdx.x * blockDim.x + threadIdx.x;
    if (idx >= M_ROWS * DINNER / 4) return;
    int d4 = (idx % (DINNER / 4)) * 4;
    int m  = idx / (DINNER / 4);
    int t  = m % LSEQ;
    int b  = m / LSEQ;

    float4 acc = *reinterpret_cast<const float4*>(conv_b + d4);
#pragma unroll
    for (int j = 0; j < DCONV; j++) {
        int tt = t - (DCONV - 1) + j;
        if (tt >= 0) {
            float4 v = *reinterpret_cast<const float4*>(
                g_xz + (size_t)(b * LSEQ + tt) * XZ_COLS + d4);
            acc.x += v.x * __ldg(conv_w + (d4 + 0) * DCONV + j);
            acc.y += v.y * __ldg(conv_w + (d4 + 1) * DCONV + j);
            acc.z += v.z * __ldg(conv_w + (d4 + 2) * DCONV + j);
            acc.w += v.w * __ldg(conv_w + (d4 + 3) * DCONV + j);
        }
    }
    float4 o;
    o.x = acc.x / (1.f + __expf(-acc.x));
    o.y = acc.y / (1.f + __expf(-acc.y));
    o.z = acc.z / (1.f + __expf(-acc.z));
    o.w = acc.w / (1.f + __expf(-acc.w));
    size_t off = (size_t)m * DINNER + d4;
    *reinterpret_cast<float4*>(g_xc + off) = o;
    reinterpret_cast<uint2*>(g_xch)[off / 4] = cvt_f16x4(o);
}

// ---------------------------------------------------------------------------
// x_proj reduce: sum partials -> g_xdbl; also emit fp16 dt-rank cols.
// ---------------------------------------------------------------------------
__global__ void xproj_reduce_kernel()
{
    int i = blockIdx.x * blockDim.x + threadIdx.x;
    if (i >= M_ROWS * XDBL_COLS) return;
    int r = i / XDBL_COLS, c = i % XDBL_COLS;
    float s = 0.f;
#pragma unroll
    for (int z = 0; z < NSLICE; z++)
        s += g_xp2[(size_t)z * M_ROWS * XPN + (size_t)r * XPN + c];
    g_xdbl[i] = s;
    if (c < DTRANK)
        g_dth[(size_t)r * DTRANK + c] = __float2half_rn(s);
}

// ---------------------------------------------------------------------------
// Chunked selective scan (pass1 / combine / pass2)
// ---------------------------------------------------------------------------
__global__ void scan_pass1(const float* __restrict__ A_log)
{
    const int lane16 = threadIdx.x & 15;
    const int grp    = threadIdx.x >> 4;
    const int b      = blockIdx.x / (DINNER / 16);
    const int d      = (blockIdx.x % (DINNER / 16)) * 16 + grp;
    const int ck     = blockIdx.y;
    const int t0     = ck * CLEN;

    const float Ad = -__expf(A_log[d * DSTATE + lane16]);

    const float* dt_p = g_dt   + ((size_t)b * LSEQ + t0) * DINNER + d;
    const float* x_p  = g_xc   + ((size_t)b * LSEQ + t0) * DINNER + d;
    const float* bc_p = g_xdbl + ((size_t)b * LSEQ + t0) * XDBL_COLS;

    float h = 0.f, p = 1.f;
    float d0 = dt_p[0], x0 = x_p[0];
    float B0 = bc_p[DTRANK + lane16];
    float d1 = dt_p[DINNER], x1 = x_p[DINNER];
    float B1 = bc_p[XDBL_COLS + DTRANK + lane16];

    for (int t = 0; t < CLEN; t++) {
        float d2 = 0.f, x2 = 0.f, B2 = 0.f;
        if (t + 2 < CLEN) {
            d2 = dt_p[(size_t)(t + 2) * DINNER];
            x2 = x_p [(size_t)(t + 2) * DINNER];
            B2 = bc_p[(size_t)(t + 2) * XDBL_COLS + DTRANK + lane16];
        }
        float dA = __expf(d0 * Ad);
        h = dA * h + (d0 * x0) * B0;
        p *= dA;
        d0 = d1; x0 = x1; B0 = B1;
        d1 = d2; x1 = x2; B1 = B2;
    }
    size_t idx = (((size_t)b * DINNER + d) * DSTATE + lane16) * NCHUNK + ck;
    g_P[idx] = p;
    g_S[idx] = h;
}

__global__ void scan_combine()
{
    int i = blockIdx.x * blockDim.x + threadIdx.x;
    if (i >= B_SZ * DINNER * DSTATE) return;
    size_t base = (size_t)i * NCHUNK;
    float h = 0.f;
#pragma unroll
    for (int c = 0; c < NCHUNK; c++) {
        g_h0[base + c] = h;
        h = g_S[base + c] + g_P[base + c] * h;
    }
}

__global__ void scan_pass2(const float* __restrict__ A_log,
                           const float* __restrict__ D_param)
{
    const int lane16 = threadIdx.x & 15;
    const int grp    = threadIdx.x >> 4;
    const int b      = blockIdx.x / (DINNER / 16);
    const int d      = (blockIdx.x % (DINNER / 16)) * 16 + grp;
    const int ck     = blockIdx.y;
    const int t0     = ck * CLEN;

    const float Ad = -__expf(A_log[d * DSTATE + lane16]);
    const float Dd = D_param[d];

    const float* dt_p = g_dt   + ((size_t)b * LSEQ + t0) * DINNER + d;
    const float* x_p  = g_xc   + ((size_t)b * LSEQ + t0) * DINNER + d;
    const float* bc_p = g_xdbl + ((size_t)b * LSEQ + t0) * XDBL_COLS;
    float*       y_p  = g_y    + ((size_t)b * LSEQ + t0) * DINNER + d;

    float h = g_h0[(((size_t)b * DINNER + d) * DSTATE + lane16) * NCHUNK + ck];

    float d0 = dt_p[0], x0 = x_p[0];
    float B0 = bc_p[DTRANK + lane16];
    float C0 = bc_p[DTRANK + DSTATE + lane16];
    float d1 = dt_p[DINNER], x1 = x_p[DINNER];
    float B1 = bc_p[XDBL_COLS + DTRANK + lane16];
    float C1 = bc_p[XDBL_COLS + DTRANK + DSTATE + lane16];

    for (int t = 0; t < CLEN; t++) {
        float d2 = 0.f, x2 = 0.f, B2 = 0.f, C2 = 0.f;
        if (t + 2 < CLEN) {
            d2 = dt_p[(size_t)(t + 2) * DINNER];
            x2 = x_p [(size_t)(t + 2) * DINNER];
            B2 = bc_p[(size_t)(t + 2) * XDBL_COLS + DTRANK + lane16];
            C2 = bc_p[(size_t)(t + 2) * XDBL_COLS + DTRANK + DSTATE + lane16];
        }
        float dA = __expf(d0 * Ad);
        h = dA * h + (d0 * x0) * B0;
        float p = h * C0;
        p += __shfl_xor_sync(0xffffffffu, p, 1);
        p += __shfl_xor_sync(0xffffffffu, p, 2);
        p += __shfl_xor_sync(0xffffffffu, p, 4);
        p += __shfl_xor_sync(0xffffffffu, p, 8);
        if (lane16 == 0)
            y_p[(size_t)t * DINNER] = p + Dd * x0;
        d0 = d1; x0 = x1; B0 = B1; C0 = C1;
        d1 = d2; x1 = x2; B1 = B2; C1 = C2;
    }
}

// ---------------------------------------------------------------------------
// Gate + fp16 convert (coalesced, standalone)
// ---------------------------------------------------------------------------
__global__ void gate_cvt_kernel()
{
    int idx = blockIdx.x * blockDim.x + threadIdx.x;
    if (idx >= M_ROWS * DINNER / 4) return;
    int d4 = (idx % (DINNER / 4)) * 4;
    int m  = idx / (DINNER / 4);
    float4 z = *reinterpret_cast<const float4*>(g_xz + (size_t)m * XZ_COLS + DINNER + d4);
    float4 y = *reinterpret_cast<const float4*>(g_y + (size_t)m * DINNER + d4);
    float4 v;
    v.x = y.x * (z.x / (1.f + __expf(-z.x)));
    v.y = y.y * (z.y / (1.f + __expf(-z.y)));
    v.z = y.z * (z.z / (1.f + __expf(-z.z)));
    v.w = y.w * (z.w / (1.f + __expf(-z.w)));
    size_t off = ((size_t)m * DINNER + d4) / 4;
    reinterpret_cast<uint2*>(g_yh)[off] = cvt_f16x4(v);
}

// ---------------------------------------------------------------------------
// Launch
// ---------------------------------------------------------------------------
extern "C" void kernel_launch(void* const* d_in, const int* in_sizes, int n_in,
                              void* d_out, int out_size)
{
    const float* x         = (const float*)d_in[0];
    const float* in_proj_w = (const float*)d_in[1];
    const float* conv_w    = (const float*)d_in[2];
    const float* conv_b    = (const float*)d_in[3];
    const float* x_proj_w  = (const float*)d_in[4];
    const float* dt_proj_w = (const float*)d_in[5];
    const float* dt_proj_b = (const float*)d_in[6];
    const float* A_log     = (const float*)d_in[7];
    const float* D_param   = (const float*)d_in[8];
    const float* out_proj_w= (const float*)d_in[9];
    float* out = (float*)d_out;

    float *xz, *dt, *xp2;
    cudaGetSymbolAddress((void**)&xz,  g_xz);
    cudaGetSymbolAddress((void**)&dt,  g_dt);
    cudaGetSymbolAddress((void**)&xp2, g_xp2);
    __half *xh, *wih, *yh, *woh, *xch, *xwh, *dth, *dwh;
    cudaGetSymbolAddress((void**)&xh,  g_xh);
    cudaGetSymbolAddress((void**)&wih, g_wih);
    cudaGetSymbolAddress((void**)&yh,  g_yh);
    cudaGetSymbolAddress((void**)&woh, g_woh);
    cudaGetSymbolAddress((void**)&xch, g_xch);
    cudaGetSymbolAddress((void**)&xwh, g_xwh);
    cudaGetSymbolAddress((void**)&dth, g_dth);
    cudaGetSymbolAddress((void**)&dwh, g_dwh);

    cudaFuncSetAttribute(tc_gemm_kernel<0>, cudaFuncAttributeMaxDynamicSharedMemorySize, TCSMEM);
    cudaFuncSetAttribute(tc_gemm_kernel<1>, cudaFuncAttributeMaxDynamicSharedMemorySize, TCSMEM);

    // 0) merged fp32 -> fp16 conversions
    {
        int n = CVT_N1 + CVT_N2 + CVT_N3 + CVT_N4 + CVT_N5;
        cvt_all_kernel<<<(n + 255) / 256, 256>>>(x, in_proj_w, out_proj_w, x_proj_w, dt_proj_w);
    }

    // 1) in_proj: xz = x * Wi^T
    {
        dim3 grid(XZ_COLS / TCBN, M_ROWS / TCBM, 1);
        tc_gemm_kernel<0><<<grid, 128, TCSMEM>>>(DMODEL, DMODEL,
            xh, wih, xz, XZ_COLS, 0, nullptr);
    }

    // 2) conv + silu (+ fp16 emit)
    {
        int n = M_ROWS * DINNER / 4;
        conv_silu_kernel<<<(n + 255) / 256, 256>>>(conv_w, conv_b);
    }

    // 3) x_proj on tensor cores, split-K x8; then reduce (+ fp16 dt emit)
    {
        dim3 grid(1, M_ROWS / TCBM, NSLICE);
        tc_gemm_kernel<0><<<grid, 128, TCSMEM>>>(DINNER, KSLICE,
            xch, xwh, xp2, XPN, (size_t)M_ROWS * XPN, nullptr);
        int n = M_ROWS * XDBL_COLS;
        xproj_reduce_kernel<<<(n + 255) / 256, 256>>>();
    }

    // 4) dt_proj on tensor cores (K=64, single chunk) + bias + softplus
    {
        dim3 grid(DINNER / TCBN, M_ROWS / TCBM, 1);
        tc_gemm_kernel<1><<<grid, 128, TCSMEM>>>(DTRANK, DTRANK,
            dth, dwh, dt, DINNER, 0, dt_proj_b);
    }

    // 5) chunked parallel scan (NCHUNK=16)
    {
        dim3 grid(B_SZ * DINNER / 16, NCHUNK);
        scan_pass1<<<grid, 256>>>(A_log);
        int n = B_SZ * DINNER * DSTATE;
        scan_combine<<<(n + 255) / 256, 256>>>();
        scan_pass2<<<grid, 256>>>(A_log, D_param);
    }

    // 6) gate + fp16 convert
    {
        int n = M_ROWS * DINNER / 4;
        gate_cvt_kernel<<<(n + 255) / 256, 256>>>();
    }

    // 7) out_proj
    {
        dim3 grid(DMODEL / TCBN, M_ROWS / TCBM, 1);
        tc_gemm_kernel<0><<<grid, 128, TCSMEM>>>(DINNER, DINNER,
            yh, woh, out, DMODEL, 0, nullptr);
    }
}

// round 16
// speedup vs baseline: 1.5817x; 1.0590x over previous
#include <cuda_runtime.h>
#include <cuda_fp16.h>
#include <math.h>
#include <stdint.h>

// ---------------------------------------------------------------------------
// Problem constants
// ---------------------------------------------------------------------------
#define B_SZ    2
#define LSEQ    2048
#define DMODEL  1024
#define DINNER  2048
#define DSTATE  16
#define DTRANK  64
#define DCONV   4
#define M_ROWS  (B_SZ * LSEQ)            // 4096
#define XZ_COLS (2 * DINNER)             // 4096
#define XDBL_COLS (DTRANK + 2 * DSTATE)  // 96

#define NCHUNK  16
#define CLEN    (LSEQ / NCHUNK)          // 128
#define NSLICE  8
#define KSLICE  (DINNER / NSLICE)        // 256
#define XPN     128                      // padded N for x_proj tc-gemm

#define CTCH    32                       // conv t-chunk per thread
#define NCOL4   (DINNER / 4)             // 512

// ---------------------------------------------------------------------------
// Scratch
// ---------------------------------------------------------------------------
__device__ float g_xz  [(size_t)M_ROWS * XZ_COLS];
__device__ float g_xc  [(size_t)M_ROWS * DINNER];
__device__ float g_xdbl[(size_t)M_ROWS * XDBL_COLS];
__device__ float g_dt  [(size_t)M_ROWS * DINNER];
__device__ float g_y   [(size_t)M_ROWS * DINNER];
__device__ float g_xp2 [(size_t)NSLICE * M_ROWS * XPN];   // x_proj partials (padded)

__device__ float g_P [(size_t)B_SZ * DINNER * DSTATE * NCHUNK];
__device__ float g_S [(size_t)B_SZ * DINNER * DSTATE * NCHUNK];
__device__ float g_h0[(size_t)B_SZ * DINNER * DSTATE * NCHUNK];

// fp16 GEMM operands
__device__ __half g_xh [(size_t)M_ROWS * DMODEL];
__device__ __half g_wih[(size_t)XZ_COLS * DMODEL];
__device__ __half g_yh [(size_t)M_ROWS * DINNER];
__device__ __half g_woh[(size_t)DMODEL * DINNER];
__device__ __half g_xch[(size_t)M_ROWS * DINNER];
__device__ __half g_xwh[(size_t)XPN * DINNER];            // rows 96..127 stay zero
__device__ __half g_dth[(size_t)M_ROWS * DTRANK];
__device__ __half g_dwh[(size_t)DINNER * DTRANK];

// ---------------------------------------------------------------------------
// PTX helpers
// ---------------------------------------------------------------------------
__device__ __forceinline__ uint32_t smem_u32(const void* p) {
    uint32_t a;
    asm("{ .reg .u64 t; cvta.to.shared.u64 t, %1; cvt.u32.u64 %0, t; }" : "=r"(a) : "l"(p));
    return a;
}
__device__ __forceinline__ void cp_async16(uint32_t saddr, const void* gaddr) {
    asm volatile("cp.async.cg.shared.global [%0], [%1], 16;" :: "r"(saddr), "l"(gaddr));
}
#define CP_COMMIT()  asm volatile("cp.async.commit_group;" ::: "memory")
#define CP_WAIT1()   asm volatile("cp.async.wait_group 1;" ::: "memory")

__device__ __forceinline__ void ldsm_x4(uint32_t (&r)[4], uint32_t addr) {
    asm volatile("ldmatrix.sync.aligned.m8n8.x4.shared.b16 {%0,%1,%2,%3}, [%4];"
        : "=r"(r[0]), "=r"(r[1]), "=r"(r[2]), "=r"(r[3]) : "r"(addr));
}
__device__ __forceinline__ void mma_f16(float (&d)[4],
                                        const uint32_t (&a)[4],
                                        uint32_t b0, uint32_t b1) {
    asm volatile(
        "mma.sync.aligned.m16n8k16.row.col.f32.f16.f16.f32 "
        "{%0,%1,%2,%3}, {%4,%5,%6,%7}, {%8,%9}, {%0,%1,%2,%3};"
        : "+f"(d[0]), "+f"(d[1]), "+f"(d[2]), "+f"(d[3])
        : "r"(a[0]), "r"(a[1]), "r"(a[2]), "r"(a[3]), "r"(b0), "r"(b1));
}

__device__ __forceinline__ uint2 cvt_f16x4(float4 v) {
    __half2 h01 = __floats2half2_rn(v.x, v.y);
    __half2 h23 = __floats2half2_rn(v.z, v.w);
    uint2 o;
    o.x = *reinterpret_cast<uint32_t*>(&h01);
    o.y = *reinterpret_cast<uint32_t*>(&h23);
    return o;
}

// ---------------------------------------------------------------------------
// fp16 TC GEMM: C[M,N](+slice) = A[M,K-range]*B[N,K-range]^T  (single pass)
// 4-warp 128x128 tile, warp tile 64x64, BK=64, 2-stage cp.async ring.
// ---------------------------------------------------------------------------
#define TCBM 128
#define TCBN 128
#define TCBK 64
#define PITCHB 144                        // 128B data + 16B pad
#define OPTILE (TCBM * PITCHB)            // 18432 B
#define STAGEB (2 * OPTILE)               // 36864 B (A, B)
#define TCSMEM (2 * STAGEB)               // 73728 B

__device__ __forceinline__ void fill_op128(uint32_t sbase, const __half* g,
                                           int grow0, int lda, int k0, int tid) {
#pragma unroll
    for (int t = 0; t < 8; t++) {
        int u = tid + t * 128;            // 1024 chunks of 16B
        int r = u >> 3, seg = u & 7;
        const __half* gp = g + (size_t)(grow0 + r) * lda + k0 + seg * 8;
        cp_async16(sbase + r * PITCHB + seg * 16, gp);
    }
}
__device__ __forceinline__ void fill_stage(uint32_t s, const __half* A,
                                           const __half* B,
                                           int mrow, int ncol, int lda, int k0, int tid) {
    fill_op128(s,          A, mrow, lda, k0, tid);
    fill_op128(s + OPTILE, B, ncol, lda, k0, tid);
}

template<int EPI>
__global__ void __launch_bounds__(128, 2)
tc_gemm_kernel(int lda, int klen,
               const __half* __restrict__ A, const __half* __restrict__ B,
               float* __restrict__ C, int ldc, size_t c_slice_stride,
               const float* __restrict__ bias)
{
    extern __shared__ char smem[];
    const uint32_t sb = smem_u32(smem);

    const int tid  = threadIdx.x;
    const int lane = tid & 31;
    const int w    = tid >> 5;
    const int wm   = w & 1;
    const int wn   = w >> 1;
    const int mrow = blockIdx.y * TCBM;
    const int ncol = blockIdx.x * TCBN;
    const int kbeg = blockIdx.z * klen;
    C += (size_t)blockIdx.z * c_slice_stride;

    float acc[4][8][4];
#pragma unroll
    for (int i = 0; i < 4; i++)
#pragma unroll
        for (int j = 0; j < 8; j++)
#pragma unroll
            for (int e = 0; e < 4; e++) acc[i][j][e] = 0.f;

    const int nc = klen / TCBK;

    fill_stage(sb, A, B, mrow, ncol, lda, kbeg, tid);
    CP_COMMIT();

    const int a_row = (lane & 15);
    const int a_cb  = (lane >> 4);
    const int b_row = (lane & 7) + ((lane >> 4) << 3);
    const int b_cb  = (lane >> 3) & 1;

    for (int c = 0; c < nc; c++) {
        if (c + 1 < nc) {
            fill_stage(sb + ((c + 1) & 1) * STAGEB, A, B,
                       mrow, ncol, lda, kbeg + (c + 1) * TCBK, tid);
        }
        CP_COMMIT();
        CP_WAIT1();
        __syncthreads();

        const uint32_t s  = sb + (c & 1) * STAGEB;
        const uint32_t sA = s;
        const uint32_t sB = s + OPTILE;

#pragma unroll
        for (int ks = 0; ks < 4; ks++) {
            uint32_t ah[4][4], bh[4][4];
#pragma unroll
            for (int mi = 0; mi < 4; mi++) {
                uint32_t ao = (uint32_t)((wm * 64 + mi * 16 + a_row) * PITCHB + ks * 32 + a_cb * 16);
                ldsm_x4(ah[mi], sA + ao);
            }
#pragma unroll
            for (int j = 0; j < 4; j++) {
                uint32_t bo = (uint32_t)((wn * 64 + j * 16 + b_row) * PITCHB + ks * 32 + b_cb * 16);
                ldsm_x4(bh[j], sB + bo);
            }
#pragma unroll
            for (int mi = 0; mi < 4; mi++)
#pragma unroll
                for (int nj = 0; nj < 8; nj++) {
                    const int j = nj >> 1, h = (nj & 1) * 2;
                    mma_f16(acc[mi][nj], ah[mi], bh[j][h], bh[j][h + 1]);
                }
        }
        __syncthreads();
    }

    const int er = lane >> 2;
    const int ec = (lane & 3) * 2;
#pragma unroll
    for (int mi = 0; mi < 4; mi++) {
#pragma unroll
        for (int nj = 0; nj < 8; nj++) {
            int r0 = mrow + wm * 64 + mi * 16 + er;
            int cc = ncol + wn * 64 + nj * 8 + ec;
            float2 v0 = make_float2(acc[mi][nj][0], acc[mi][nj][1]);
            float2 v1 = make_float2(acc[mi][nj][2], acc[mi][nj][3]);
            if (EPI == 1) {
                float b0 = bias[cc], b1 = bias[cc + 1];
                v0.x += b0; v0.y += b1; v1.x += b0; v1.y += b1;
                v0.x = (v0.x > 20.f) ? v0.x : log1pf(__expf(v0.x));
                v0.y = (v0.y > 20.f) ? v0.y : log1pf(__expf(v0.y));
                v1.x = (v1.x > 20.f) ? v1.x : log1pf(__expf(v1.x));
                v1.y = (v1.y > 20.f) ? v1.y : log1pf(__expf(v1.y));
            }
            *reinterpret_cast<float2*>(C + (size_t)r0 * ldc + cc) = v0;
            *reinterpret_cast<float2*>(C + (size_t)(r0 + 8) * ldc + cc) = v1;
        }
    }
}

// ---------------------------------------------------------------------------
// Merged fp32 -> fp16 conversions: x, in_proj_w, out_proj_w, x_proj_w, dt_proj_w
// ---------------------------------------------------------------------------
#define CVT_N1 (M_ROWS * DMODEL / 4)
#define CVT_N2 (XZ_COLS * DMODEL / 4)
#define CVT_N3 (DMODEL * DINNER / 4)
#define CVT_N4 (XDBL_COLS * DINNER / 4)
#define CVT_N5 (DINNER * DTRANK / 4)

__global__ void cvt_all_kernel(const float* __restrict__ x,
                               const float* __restrict__ wi,
                               const float* __restrict__ wo,
                               const float* __restrict__ xw,
                               const float* __restrict__ dw)
{
    int i = blockIdx.x * blockDim.x + threadIdx.x;
    const float* src; __half* dst; int off;
    if (i < CVT_N1)                           { src = x;  dst = g_xh;  off = i; }
    else if (i < CVT_N1+CVT_N2)               { src = wi; dst = g_wih; off = i - CVT_N1; }
    else if (i < CVT_N1+CVT_N2+CVT_N3)        { src = wo; dst = g_woh; off = i - CVT_N1 - CVT_N2; }
    else if (i < CVT_N1+CVT_N2+CVT_N3+CVT_N4) { src = xw; dst = g_xwh; off = i - CVT_N1 - CVT_N2 - CVT_N3; }
    else if (i < CVT_N1+CVT_N2+CVT_N3+CVT_N4+CVT_N5) { src = dw; dst = g_dwh; off = i - CVT_N1 - CVT_N2 - CVT_N3 - CVT_N4; }
    else return;

    float4 v = reinterpret_cast<const float4*>(src)[off];
    reinterpret_cast<uint2*>(dst)[off] = cvt_f16x4(v);
}

// ---------------------------------------------------------------------------
// Depthwise causal conv1d + bias + SiLU, rolling-window (each xz elem read 1x).
// One thread per (b, t-chunk, d4 column). Tap order preserved (bit-identical).
// ---------------------------------------------------------------------------
__global__ void conv_silu_kernel(const float* __restrict__ conv_w,
                                 const float* __restrict__ conv_b)
{
    int id = blockIdx.x * blockDim.x + threadIdx.x;
    const int nck = LSEQ / CTCH;                    // 64
    if (id >= B_SZ * nck * NCOL4) return;
    int col4 = id % NCOL4;
    int rest = id / NCOL4;
    int ck = rest % nck;
    int b  = rest / nck;
    int d4 = col4 * 4;
    int t0 = ck * CTCH;

    // per-channel weights (j = 0..3 for each of 4 channels)
    float wreg[4][4];
#pragma unroll
    for (int e = 0; e < 4; e++)
#pragma unroll
        for (int j = 0; j < DCONV; j++)
            wreg[e][j] = __ldg(conv_w + (d4 + e) * DCONV + j);
    float4 bias = *reinterpret_cast<const float4*>(conv_b + d4);

    const float* xp = g_xz + ((size_t)(b * LSEQ + t0)) * XZ_COLS + d4;

    // history x[t0-3..t0-1]; zeros when out of range (matches tt>=0 skip)
    float4 zero4 = make_float4(0.f, 0.f, 0.f, 0.f);
    float4 h0 = (t0 >= 3) ? *reinterpret_cast<const float4*>(xp - 3 * XZ_COLS) : zero4;
    float4 h1 = (t0 >= 2) ? *reinterpret_cast<const float4*>(xp - 2 * XZ_COLS) : zero4;
    float4 h2 = (t0 >= 1) ? *reinterpret_cast<const float4*>(xp - 1 * XZ_COLS) : zero4;

    float* outp = g_xc + ((size_t)(b * LSEQ + t0)) * DINNER + d4;
    uint2* outh = reinterpret_cast<uint2*>(g_xch) + (((size_t)(b * LSEQ + t0)) * DINNER + d4) / 4;

#pragma unroll 4
    for (int t = 0; t < CTCH; t++) {
        float4 cur = *reinterpret_cast<const float4*>(xp + (size_t)t * XZ_COLS);
        float4 acc = bias;
        // j=0 (x[t-3]), j=1, j=2, j=3 — same order as reference
        acc.x += h0.x * wreg[0][0]; acc.y += h0.y * wreg[1][0];
        acc.z += h0.z * wreg[2][0]; acc.w += h0.w * wreg[3][0];
        acc.x += h1.x * wreg[0][1]; acc.y += h1.y * wreg[1][1];
        acc.z += h1.z * wreg[2][1]; acc.w += h1.w * wreg[3][1];
        acc.x += h2.x * wreg[0][2]; acc.y += h2.y * wreg[1][2];
        acc.z += h2.z * wreg[2][2]; acc.w += h2.w * wreg[3][2];
        acc.x += cur.x * wreg[0][3]; acc.y += cur.y * wreg[1][3];
        acc.z += cur.z * wreg[2][3]; acc.w += cur.w * wreg[3][3];
        float4 o;
        o.x = acc.x / (1.f + __expf(-acc.x));
        o.y = acc.y / (1.f + __expf(-acc.y));
        o.z = acc.z / (1.f + __expf(-acc.z));
        o.w = acc.w / (1.f + __expf(-acc.w));
        *reinterpret_cast<float4*>(outp + (size_t)t * DINNER) = o;
        outh[(size_t)t * DINNER / 4] = cvt_f16x4(o);
        h0 = h1; h1 = h2; h2 = cur;
    }
}

// ---------------------------------------------------------------------------
// x_proj reduce: sum partials -> g_xdbl; also emit fp16 dt-rank cols.
// ---------------------------------------------------------------------------
__global__ void xproj_reduce_kernel()
{
    int i = blockIdx.x * blockDim.x + threadIdx.x;
    if (i >= M_ROWS * XDBL_COLS) return;
    int r = i / XDBL_COLS, c = i % XDBL_COLS;
    float s = 0.f;
#pragma unroll
    for (int z = 0; z < NSLICE; z++)
        s += g_xp2[(size_t)z * M_ROWS * XPN + (size_t)r * XPN + c];
    g_xdbl[i] = s;
    if (c < DTRANK)
        g_dth[(size_t)r * DTRANK + c] = __float2half_rn(s);
}

// ---------------------------------------------------------------------------
// Chunked selective scan (pass1 / combine / pass2)
// ---------------------------------------------------------------------------
__global__ void scan_pass1(const float* __restrict__ A_log)
{
    const int lane16 = threadIdx.x & 15;
    const int grp    = threadIdx.x >> 4;
    const int b      = blockIdx.x / (DINNER / 16);
    const int d      = (blockIdx.x % (DINNER / 16)) * 16 + grp;
    const int ck     = blockIdx.y;
    const int t0     = ck * CLEN;

    const float Ad = -__expf(A_log[d * DSTATE + lane16]);

    const float* dt_p = g_dt   + ((size_t)b * LSEQ + t0) * DINNER + d;
    const float* x_p  = g_xc   + ((size_t)b * LSEQ + t0) * DINNER + d;
    const float* bc_p = g_xdbl + ((size_t)b * LSEQ + t0) * XDBL_COLS;

    float h = 0.f, p = 1.f;
    float d0 = dt_p[0], x0 = x_p[0];
    float B0 = bc_p[DTRANK + lane16];
    float d1 = dt_p[DINNER], x1 = x_p[DINNER];
    float B1 = bc_p[XDBL_COLS + DTRANK + lane16];

    for (int t = 0; t < CLEN; t++) {
        float d2 = 0.f, x2 = 0.f, B2 = 0.f;
        if (t + 2 < CLEN) {
            d2 = dt_p[(size_t)(t + 2) * DINNER];
            x2 = x_p [(size_t)(t + 2) * DINNER];
            B2 = bc_p[(size_t)(t + 2) * XDBL_COLS + DTRANK + lane16];
        }
        float dA = __expf(d0 * Ad);
        h = dA * h + (d0 * x0) * B0;
        p *= dA;
        d0 = d1; x0 = x1; B0 = B1;
        d1 = d2; x1 = x2; B1 = B2;
    }
    size_t idx = (((size_t)b * DINNER + d) * DSTATE + lane16) * NCHUNK + ck;
    g_P[idx] = p;
    g_S[idx] = h;
}

__global__ void scan_combine()
{
    int i = blockIdx.x * blockDim.x + threadIdx.x;
    if (i >= B_SZ * DINNER * DSTATE) return;
    size_t base = (size_t)i * NCHUNK;
    float h = 0.f;
#pragma unroll
    for (int c = 0; c < NCHUNK; c++) {
        g_h0[base + c] = h;
        h = g_S[base + c] + g_P[base + c] * h;
    }
}

__global__ void scan_pass2(const float* __restrict__ A_log,
                           const float* __restrict__ D_param)
{
    const int lane16 = threadIdx.x & 15;
    const int grp    = threadIdx.x >> 4;
    const int b      = blockIdx.x / (DINNER / 16);
    const int d      = (blockIdx.x % (DINNER / 16)) * 16 + grp;
    const int ck     = blockIdx.y;
    const int t0     = ck * CLEN;

    const float Ad = -__expf(A_log[d * DSTATE + lane16]);
    const float Dd = D_param[d];

    const float* dt_p = g_dt   + ((size_t)b * LSEQ + t0) * DINNER + d;
    const float* x_p  = g_xc   + ((size_t)b * LSEQ + t0) * DINNER + d;
    const float* bc_p = g_xdbl + ((size_t)b * LSEQ + t0) * XDBL_COLS;
    float*       y_p  = g_y    + ((size_t)b * LSEQ + t0) * DINNER + d;

    float h = g_h0[(((size_t)b * DINNER + d) * DSTATE + lane16) * NCHUNK + ck];

    float d0 = dt_p[0], x0 = x_p[0];
    float B0 = bc_p[DTRANK + lane16];
    float C0 = bc_p[DTRANK + DSTATE + lane16];
    float d1 = dt_p[DINNER], x1 = x_p[DINNER];
    float B1 = bc_p[XDBL_COLS + DTRANK + lane16];
    float C1 = bc_p[XDBL_COLS + DTRANK + DSTATE + lane16];

    for (int t = 0; t < CLEN; t++) {
        float d2 = 0.f, x2 = 0.f, B2 = 0.f, C2 = 0.f;
        if (t + 2 < CLEN) {
            d2 = dt_p[(size_t)(t + 2) * DINNER];
            x2 = x_p [(size_t)(t + 2) * DINNER];
            B2 = bc_p[(size_t)(t + 2) * XDBL_COLS + DTRANK + lane16];
            C2 = bc_p[(size_t)(t + 2) * XDBL_COLS + DTRANK + DSTATE + lane16];
        }
        float dA = __expf(d0 * Ad);
        h = dA * h + (d0 * x0) * B0;
        float p = h * C0;
        p += __shfl_xor_sync(0xffffffffu, p, 1);
        p += __shfl_xor_sync(0xffffffffu, p, 2);
        p += __shfl_xor_sync(0xffffffffu, p, 4);
        p += __shfl_xor_sync(0xffffffffu, p, 8);
        if (lane16 == 0)
            y_p[(size_t)t * DINNER] = p + Dd * x0;
        d0 = d1; x0 = x1; B0 = B1; C0 = C1;
        d1 = d2; x1 = x2; B1 = B2; C1 = C2;
    }
}

// ---------------------------------------------------------------------------
// Gate + fp16 convert (coalesced, standalone)
// ---------------------------------------------------------------------------
__global__ void gate_cvt_kernel()
{
    int idx = blockIdx.x * blockDim.x + threadIdx.x;
    if (idx >= M_ROWS * DINNER / 4) return;
    int d4 = (idx % (DINNER / 4)) * 4;
    int m  = idx / (DINNER / 4);
    float4 z = *reinterpret_cast<const float4*>(g_xz + (size_t)m * XZ_COLS + DINNER + d4);
    float4 y = *reinterpret_cast<const float4*>(g_y + (size_t)m * DINNER + d4);
    float4 v;
    v.x = y.x * (z.x / (1.f + __expf(-z.x)));
    v.y = y.y * (z.y / (1.f + __expf(-z.y)));
    v.z = y.z * (z.z / (1.f + __expf(-z.z)));
    v.w = y.w * (z.w / (1.f + __expf(-z.w)));
    size_t off = ((size_t)m * DINNER + d4) / 4;
    reinterpret_cast<uint2*>(g_yh)[off] = cvt_f16x4(v);
}

// ---------------------------------------------------------------------------
// Launch
// ---------------------------------------------------------------------------
extern "C" void kernel_launch(void* const* d_in, const int* in_sizes, int n_in,
                              void* d_out, int out_size)
{
    const float* x         = (const float*)d_in[0];
    const float* in_proj_w = (const float*)d_in[1];
    const float* conv_w    = (const float*)d_in[2];
    const float* conv_b    = (const float*)d_in[3];
    const float* x_proj_w  = (const float*)d_in[4];
    const float* dt_proj_w = (const float*)d_in[5];
    const float* dt_proj_b = (const float*)d_in[6];
    const float* A_log     = (const float*)d_in[7];
    const float* D_param   = (const float*)d_in[8];
    const float* out_proj_w= (const float*)d_in[9];
    float* out = (float*)d_out;

    float *xz, *dt, *xp2;
    cudaGetSymbolAddress((void**)&xz,  g_xz);
    cudaGetSymbolAddress((void**)&dt,  g_dt);
    cudaGetSymbolAddress((void**)&xp2, g_xp2);
    __half *xh, *wih, *yh, *woh, *xch, *xwh, *dth, *dwh;
    cudaGetSymbolAddress((void**)&xh,  g_xh);
    cudaGetSymbolAddress((void**)&wih, g_wih);
    cudaGetSymbolAddress((void**)&yh,  g_yh);
    cudaGetSymbolAddress((void**)&woh, g_woh);
    cudaGetSymbolAddress((void**)&xch, g_xch);
    cudaGetSymbolAddress((void**)&xwh, g_xwh);
    cudaGetSymbolAddress((void**)&dth, g_dth);
    cudaGetSymbolAddress((void**)&dwh, g_dwh);

    cudaFuncSetAttribute(tc_gemm_kernel<0>, cudaFuncAttributeMaxDynamicSharedMemorySize, TCSMEM);
    cudaFuncSetAttribute(tc_gemm_kernel<1>, cudaFuncAttributeMaxDynamicSharedMemorySize, TCSMEM);

    // 0) merged fp32 -> fp16 conversions
    {
        int n = CVT_N1 + CVT_N2 + CVT_N3 + CVT_N4 + CVT_N5;
        cvt_all_kernel<<<(n + 255) / 256, 256>>>(x, in_proj_w, out_proj_w, x_proj_w, dt_proj_w);
    }

    // 1) in_proj: xz = x * Wi^T
    {
        dim3 grid(XZ_COLS / TCBN, M_ROWS / TCBM, 1);
        tc_gemm_kernel<0><<<grid, 128, TCSMEM>>>(DMODEL, DMODEL,
            xh, wih, xz, XZ_COLS, 0, nullptr);
    }

    // 2) conv + silu (rolling window, + fp16 emit)
    {
        int n = B_SZ * (LSEQ / CTCH) * NCOL4;      // 65536
        conv_silu_kernel<<<(n + 255) / 256, 256>>>(conv_w, conv_b);
    }

    // 3) x_proj on tensor cores, split-K x8; then reduce (+ fp16 dt emit)
    {
        dim3 grid(1, M_ROWS / TCBM, NSLICE);
        tc_gemm_kernel<0><<<grid, 128, TCSMEM>>>(DINNER, KSLICE,
            xch, xwh, xp2, XPN, (size_t)M_ROWS * XPN, nullptr);
        int n = M_ROWS * XDBL_COLS;
        xproj_reduce_kernel<<<(n + 255) / 256, 256>>>();
    }

    // 4) dt_proj on tensor cores (K=64, single chunk) + bias + softplus
    {
        dim3 grid(DINNER / TCBN, M_ROWS / TCBM, 1);
        tc_gemm_kernel<1><<<grid, 128, TCSMEM>>>(DTRANK, DTRANK,
            dth, dwh, dt, DINNER, 0, dt_proj_b);
    }

    // 5) chunked parallel scan (NCHUNK=16)
    {
        dim3 grid(B_SZ * DINNER / 16, NCHUNK);
        scan_pass1<<<grid, 256>>>(A_log);
        int n = B_SZ * DINNER * DSTATE;
        scan_combine<<<(n + 255) / 256, 256>>>();
        scan_pass2<<<grid, 256>>>(A_log, D_param);
    }

    // 6) gate + fp16 convert
    {
        int n = M_ROWS * DINNER / 4;
        gate_cvt_kernel<<<(n + 255) / 256, 256>>>();
    }

    // 7) out_proj
    {
        dim3 grid(DMODEL / TCBN, M_ROWS / TCBM, 1);
        tc_gemm_kernel<0><<<grid, 128, TCSMEM>>>(DINNER, DINNER,
            yh, woh, out, DMODEL, 0, nullptr);
    }
}